// round 2
// baseline (speedup 1.0000x reference)
#include <cuda_runtime.h>

// Problem constants
#define BB 4
#define SS 2048
#define DM 1024
#define HH 16
#define HD 64
#define MROWS (BB * SS)   // 8192

// Scratch (allocation-free rule: __device__ globals)
__device__ float g_Q[MROWS * DM];
__device__ float g_K[MROWS * DM];
__device__ float g_V[MROWS * DM];
__device__ float g_X[MROWS * DM];

// ---------------------------------------------------------------------------
// C[M,N] = A[M,K] * W[N,K]^T + bias[N]   (nn.Linear),  K = N = DM = 1024
// 128x128 tile, BK=16, 256 threads, 8x8 per-thread microtile.
// ---------------------------------------------------------------------------
__global__ __launch_bounds__(256) void sgemm_nt(
    const float* __restrict__ A, const float* __restrict__ W,
    const float* __restrict__ bias, float* __restrict__ C)
{
    constexpr int BM = 128, BN = 128, BK = 16, LDT = BM + 4;
    __shared__ float As[BK][LDT];
    __shared__ float Bs[BK][LDT];

    const int tid = threadIdx.x;
    const int tx = tid & 15;          // 0..15 -> N direction
    const int ty = tid >> 4;          // 0..15 -> M direction
    const int bm = blockIdx.y * BM;
    const int bn = blockIdx.x * BN;

    const int lr = tid >> 2;          // 0..63 : load row (and +64)
    const int lc = (tid & 3) << 2;    // 0,4,8,12 : load k-offset

    float acc[8][8];
#pragma unroll
    for (int i = 0; i < 8; i++)
#pragma unroll
        for (int j = 0; j < 8; j++) acc[i][j] = 0.0f;

    const float* Aptr = A + (size_t)(bm + lr) * DM + lc;
    const float* Wptr = W + (size_t)(bn + lr) * DM + lc;

    for (int k0 = 0; k0 < DM; k0 += BK) {
#pragma unroll
        for (int i = 0; i < 2; i++) {
            float4 va = *(const float4*)(Aptr + (size_t)i * 64 * DM + k0);
            As[lc + 0][lr + i * 64] = va.x;
            As[lc + 1][lr + i * 64] = va.y;
            As[lc + 2][lr + i * 64] = va.z;
            As[lc + 3][lr + i * 64] = va.w;
            float4 vb = *(const float4*)(Wptr + (size_t)i * 64 * DM + k0);
            Bs[lc + 0][lr + i * 64] = vb.x;
            Bs[lc + 1][lr + i * 64] = vb.y;
            Bs[lc + 2][lr + i * 64] = vb.z;
            Bs[lc + 3][lr + i * 64] = vb.w;
        }
        __syncthreads();
#pragma unroll
        for (int k = 0; k < BK; k++) {
            float a[8], b[8];
            *(float4*)&a[0] = *(const float4*)&As[k][ty * 8];
            *(float4*)&a[4] = *(const float4*)&As[k][ty * 8 + 4];
            *(float4*)&b[0] = *(const float4*)&Bs[k][tx * 8];
            *(float4*)&b[4] = *(const float4*)&Bs[k][tx * 8 + 4];
#pragma unroll
            for (int i = 0; i < 8; i++)
#pragma unroll
                for (int j = 0; j < 8; j++)
                    acc[i][j] += a[i] * b[j];
        }
        __syncthreads();
    }

    const float4 bv0 = *(const float4*)&bias[bn + tx * 8];
    const float4 bv1 = *(const float4*)&bias[bn + tx * 8 + 4];
#pragma unroll
    for (int i = 0; i < 8; i++) {
        float* cp = C + (size_t)(bm + ty * 8 + i) * DM + bn + tx * 8;
        float4 o0, o1;
        o0.x = acc[i][0] + bv0.x; o0.y = acc[i][1] + bv0.y;
        o0.z = acc[i][2] + bv0.z; o0.w = acc[i][3] + bv0.w;
        o1.x = acc[i][4] + bv1.x; o1.y = acc[i][5] + bv1.y;
        o1.z = acc[i][6] + bv1.z; o1.w = acc[i][7] + bv1.w;
        *(float4*)&cp[0] = o0;
        *(float4*)&cp[4] = o1;
    }
}

// ---------------------------------------------------------------------------
// Flash attention, fp32. One block per (64-query tile, head, batch).
// 256 threads = 16x16 grid, 4x4 register tiles for QK^T and PV.
// Online softmax; per-row stats reduced with shuffles (16 lanes per row
// are contiguous within a warp).
// ---------------------------------------------------------------------------
#define TP 68   // padded tile stride (64 + 4)

__global__ __launch_bounds__(256) void attn_kernel(
    const float* __restrict__ Q, const float* __restrict__ K,
    const float* __restrict__ V, float* __restrict__ X)
{
    extern __shared__ float sm[];
    float* Qs   = sm;                 // 64*TP
    float* Ks   = Qs + 64 * TP;       // 64*TP
    float* Vs   = Ks + 64 * TP;       // 64*TP
    float* Ps   = Vs + 64 * TP;       // 64*TP
    float* rmax = Ps + 64 * TP;       // 64
    float* rsum = rmax + 64;          // 64

    const int tid = threadIdx.x;
    const int tx = tid & 15;          // key-col / headdim-col group
    const int ty = tid >> 4;          // query-row group
    const int qb = blockIdx.x;
    const int h  = blockIdx.y;
    const int b  = blockIdx.z;
    const size_t headbase = ((size_t)b * SS) * DM + (size_t)h * HD;

    // Load Q tile [64 x 64]
#pragma unroll
    for (int i = 0; i < 4; i++) {
        int f = tid + i * 256;
        int r = f >> 4, d4 = (f & 15) << 2;
        *(float4*)&Qs[r * TP + d4] =
            *(const float4*)&Q[headbase + (size_t)(qb * 64 + r) * DM + d4];
    }
    if (tid < 64) { rmax[tid] = -3.0e38f; rsum[tid] = 0.0f; }

    float o[4][4];
#pragma unroll
    for (int i = 0; i < 4; i++)
#pragma unroll
        for (int j = 0; j < 4; j++) o[i][j] = 0.0f;

    __syncthreads();

    const float inv_scale = 0.03125f;   // 1/sqrt(D) = 1/32  (module scales by hid_dim!)

    for (int kt = 0; kt < SS / 64; kt++) {
        // Load K,V tiles [64 x 64]
#pragma unroll
        for (int i = 0; i < 4; i++) {
            int f = tid + i * 256;
            int r = f >> 4, d4 = (f & 15) << 2;
            size_t g = headbase + (size_t)(kt * 64 + r) * DM + d4;
            *(float4*)&Ks[r * TP + d4] = *(const float4*)&K[g];
            *(float4*)&Vs[r * TP + d4] = *(const float4*)&V[g];
        }
        __syncthreads();

        // Scores: s[i][j] = Q[ty*4+i] . K[tx*4+j]
        float s[4][4];
#pragma unroll
        for (int i = 0; i < 4; i++)
#pragma unroll
            for (int j = 0; j < 4; j++) s[i][j] = 0.0f;

#pragma unroll
        for (int d0 = 0; d0 < 64; d0 += 4) {
            float4 qv[4], kv[4];
#pragma unroll
            for (int i = 0; i < 4; i++)
                qv[i] = *(const float4*)&Qs[(ty * 4 + i) * TP + d0];
#pragma unroll
            for (int j = 0; j < 4; j++)
                kv[j] = *(const float4*)&Ks[(tx * 4 + j) * TP + d0];
#pragma unroll
            for (int i = 0; i < 4; i++)
#pragma unroll
                for (int j = 0; j < 4; j++)
                    s[i][j] += qv[i].x * kv[j].x + qv[i].y * kv[j].y +
                               qv[i].z * kv[j].z + qv[i].w * kv[j].w;
        }

        // Online softmax per row (16 tx-lanes share a row, same warp half)
#pragma unroll
        for (int i = 0; i < 4; i++) {
            int r = ty * 4 + i;
            float tmax = -3.0e38f;
#pragma unroll
            for (int j = 0; j < 4; j++) {
                s[i][j] *= inv_scale;
                tmax = fmaxf(tmax, s[i][j]);
            }
#pragma unroll
            for (int off = 8; off > 0; off >>= 1)
                tmax = fmaxf(tmax, __shfl_xor_sync(0xffffffffu, tmax, off));

            float mold = rmax[r];
            float mnew = fmaxf(mold, tmax);
            float factor = __expf(mold - mnew);

            float4 pv;
            pv.x = __expf(s[i][0] - mnew);
            pv.y = __expf(s[i][1] - mnew);
            pv.z = __expf(s[i][2] - mnew);
            pv.w = __expf(s[i][3] - mnew);
            float tsum = pv.x + pv.y + pv.z + pv.w;
#pragma unroll
            for (int off = 8; off > 0; off >>= 1)
                tsum += __shfl_xor_sync(0xffffffffu, tsum, off);

            *(float4*)&Ps[r * TP + tx * 4] = pv;
#pragma unroll
            for (int j = 0; j < 4; j++) o[i][j] *= factor;
            if (tx == 0) {
                rmax[r] = mnew;
                rsum[r] = rsum[r] * factor + tsum;
            }
        }
        __syncthreads();

        // O += P * V   (o cols = headdim tx*4+j)
#pragma unroll
        for (int c0 = 0; c0 < 64; c0 += 4) {
            float4 pr[4], vv[4];
#pragma unroll
            for (int i = 0; i < 4; i++)
                pr[i] = *(const float4*)&Ps[(ty * 4 + i) * TP + c0];
#pragma unroll
            for (int k = 0; k < 4; k++)
                vv[k] = *(const float4*)&Vs[(c0 + k) * TP + tx * 4];
#pragma unroll
            for (int i = 0; i < 4; i++) {
                o[i][0] += pr[i].x * vv[0].x + pr[i].y * vv[1].x +
                           pr[i].z * vv[2].x + pr[i].w * vv[3].x;
                o[i][1] += pr[i].x * vv[0].y + pr[i].y * vv[1].y +
                           pr[i].z * vv[2].y + pr[i].w * vv[3].y;
                o[i][2] += pr[i].x * vv[0].z + pr[i].y * vv[1].z +
                           pr[i].z * vv[2].z + pr[i].w * vv[3].z;
                o[i][3] += pr[i].x * vv[0].w + pr[i].y * vv[1].w +
                           pr[i].z * vv[2].w + pr[i].w * vv[3].w;
            }
        }
        __syncthreads();
    }

    // Normalize and store (concat-heads layout == [B,S,D] with head offset)
#pragma unroll
    for (int i = 0; i < 4; i++) {
        int r = ty * 4 + i;
        float inv = 1.0f / rsum[r];
        float4 ov;
        ov.x = o[i][0] * inv; ov.y = o[i][1] * inv;
        ov.z = o[i][2] * inv; ov.w = o[i][3] * inv;
        *(float4*)&X[headbase + (size_t)(qb * 64 + r) * DM + tx * 4] = ov;
    }
}

// ---------------------------------------------------------------------------
extern "C" void kernel_launch(void* const* d_in, const int* in_sizes, int n_in,
                              void* d_out, int out_size)
{
    const float* query = (const float*)d_in[0];
    const float* key   = (const float*)d_in[1];
    const float* value = (const float*)d_in[2];
    const float* Wq    = (const float*)d_in[3];
    const float* bq    = (const float*)d_in[4];
    const float* Wk    = (const float*)d_in[5];
    const float* bk    = (const float*)d_in[6];
    const float* Wv    = (const float*)d_in[7];
    const float* bv    = (const float*)d_in[8];
    const float* Wo    = (const float*)d_in[9];
    const float* bo    = (const float*)d_in[10];
    float* out = (float*)d_out;

    float *qp, *kp, *vp, *xp;
    cudaGetSymbolAddress((void**)&qp, g_Q);
    cudaGetSymbolAddress((void**)&kp, g_K);
    cudaGetSymbolAddress((void**)&vp, g_V);
    cudaGetSymbolAddress((void**)&xp, g_X);

    dim3 gemm_grid(DM / 128, MROWS / 128);   // (8, 64)

    sgemm_nt<<<gemm_grid, 256>>>(query, Wq, bq, qp);
    sgemm_nt<<<gemm_grid, 256>>>(key,   Wk, bk, kp);
    sgemm_nt<<<gemm_grid, 256>>>(value, Wv, bv, vp);

    int smem_bytes = (4 * 64 * TP + 128) * (int)sizeof(float);   // ~70 KB
    cudaFuncSetAttribute(attn_kernel,
                         cudaFuncAttributeMaxDynamicSharedMemorySize, smem_bytes);
    attn_kernel<<<dim3(SS / 64, HH, BB), 256, smem_bytes>>>(qp, kp, vp, xp);

    sgemm_nt<<<gemm_grid, 256>>>(xp, Wo, bo, out);
}

// round 4
// speedup vs baseline: 1.2098x; 1.2098x over previous
#include <cuda_runtime.h>
#include <cuda_bf16.h>
#include <cstdint>

// Problem constants
#define BB 4
#define SS 2048
#define DM 1024
#define HH 16
#define HD 64
#define MROWS (BB * SS)   // 8192

// Scratch (allocation-free rule: __device__ globals)
__device__ float g_Q[MROWS * DM];
__device__ float g_K[MROWS * DM];
__device__ float g_V[MROWS * DM];
__device__ float g_X[MROWS * DM];
__device__ __nv_bfloat16 g_Ah[MROWS * DM];
__device__ __nv_bfloat16 g_Al[MROWS * DM];
__device__ __nv_bfloat16 g_Wh[DM * DM];
__device__ __nv_bfloat16 g_Wl[DM * DM];

// ---------------------------------------------------------------------------
// Portable (sm_80+) tensor-core helpers: ldmatrix / mma.sync / cp.async
// ---------------------------------------------------------------------------
__device__ __forceinline__ uint32_t smem_to_u32(const void* p) {
    uint32_t a;
    asm("{ .reg .u64 t; cvta.to.shared.u64 t, %1; cvt.u32.u64 %0, t; }"
        : "=r"(a) : "l"(p));
    return a;
}

__device__ __forceinline__ void ldsm_x4(uint32_t& r0, uint32_t& r1,
                                        uint32_t& r2, uint32_t& r3,
                                        uint32_t addr) {
    asm volatile("ldmatrix.sync.aligned.m8n8.x4.shared.b16 {%0,%1,%2,%3}, [%4];"
                 : "=r"(r0), "=r"(r1), "=r"(r2), "=r"(r3) : "r"(addr));
}

__device__ __forceinline__ void mma_bf16(float* c, const uint32_t* a,
                                         const uint32_t* b) {
    asm volatile(
        "mma.sync.aligned.m16n8k16.row.col.f32.bf16.bf16.f32 "
        "{%0,%1,%2,%3}, {%4,%5,%6,%7}, {%8,%9}, {%0,%1,%2,%3};"
        : "+f"(c[0]), "+f"(c[1]), "+f"(c[2]), "+f"(c[3])
        : "r"(a[0]), "r"(a[1]), "r"(a[2]), "r"(a[3]), "r"(b[0]), "r"(b[1]));
}

#define CP_ASYNC_16(smem_u32, gptr) \
    asm volatile("cp.async.cg.shared.global [%0], [%1], 16;" \
        :: "r"(smem_u32), "l"(gptr) : "memory")
#define CP_ASYNC_COMMIT() asm volatile("cp.async.commit_group;" ::: "memory")
#define CP_ASYNC_WAIT1() asm volatile("cp.async.wait_group 1;" ::: "memory")
#define CP_ASYNC_WAIT0() asm volatile("cp.async.wait_group 0;" ::: "memory")

// ---------------------------------------------------------------------------
// Split fp32 -> (bf16 hi, bf16 lo):  x = hi + lo + O(2^-17 x)
// ---------------------------------------------------------------------------
__global__ __launch_bounds__(256) void split_bf16_kernel(
    const float* __restrict__ x, __nv_bfloat16* __restrict__ hi,
    __nv_bfloat16* __restrict__ lo, int n4)
{
    int i = blockIdx.x * blockDim.x + threadIdx.x;
    int stride = gridDim.x * blockDim.x;
    for (; i < n4; i += stride) {
        float4 v = ((const float4*)x)[i];
        __nv_bfloat16 h0 = __float2bfloat16_rn(v.x);
        __nv_bfloat16 h1 = __float2bfloat16_rn(v.y);
        __nv_bfloat16 h2 = __float2bfloat16_rn(v.z);
        __nv_bfloat16 h3 = __float2bfloat16_rn(v.w);
        __nv_bfloat16 l0 = __float2bfloat16_rn(v.x - __bfloat162float(h0));
        __nv_bfloat16 l1 = __float2bfloat16_rn(v.y - __bfloat162float(h1));
        __nv_bfloat16 l2 = __float2bfloat16_rn(v.z - __bfloat162float(h2));
        __nv_bfloat16 l3 = __float2bfloat16_rn(v.w - __bfloat162float(h3));
        __nv_bfloat162* hp = (__nv_bfloat162*)hi;
        __nv_bfloat162* lp = (__nv_bfloat162*)lo;
        hp[i * 2]     = __nv_bfloat162(h0, h1);
        hp[i * 2 + 1] = __nv_bfloat162(h2, h3);
        lp[i * 2]     = __nv_bfloat162(l0, l1);
        lp[i * 2 + 1] = __nv_bfloat162(l2, l3);
    }
}

// ---------------------------------------------------------------------------
// HMMA GEMM: C[M,N] = (Ah+Al)[M,K] @ (Wh+Wl)[N,K]^T + bias[N]
// 3-MMA split: Ah@Wh + Ah@Wl + Al@Wh.
// Block tile 128x128; 8 warps, each 64x32 via m16n8k16 fragments.
// BK=32, double-buffered cp.async smem (stride 40 bf16 -> conflict-free).
// ---------------------------------------------------------------------------
#define SA    40                         // smem row stride (bf16 elements)
#define TILEB (128 * SA * 2)             // 10240 B per 128x32 tile
#define STAGEB (4 * TILEB)               // Ah, Al, Bh, Bl
#define GEMM_SMEM (2 * STAGEB)           // 81920 B
#define BKC   32
#define NCH   (DM / BKC)                 // 32

__global__ __launch_bounds__(256, 1) void gemm_mma(
    const __nv_bfloat16* __restrict__ Ah, const __nv_bfloat16* __restrict__ Al,
    const __nv_bfloat16* __restrict__ Wh, const __nv_bfloat16* __restrict__ Wl,
    const float* __restrict__ bias, float* __restrict__ C)
{
    extern __shared__ char smem[];
    const uint32_t sb = smem_to_u32(smem);
    const int tid  = threadIdx.x;
    const int wid  = tid >> 5;
    const int lane = tid & 31;
    const int bm = blockIdx.y * 128;
    const int bn = blockIdx.x * 128;
    const int wm = (wid >> 2) * 64;     // warp M offset within tile (0 or 64)
    const int wn = (wid & 3) * 32;      // warp N offset within tile

    // ---- loader mapping: thread -> (row, 16-elt group) ----
    const int lrow  = tid >> 1;          // 0..127
    const int lcol0 = (tid & 1) * 16;    // 0 or 16
    const char* gAh = (const char*)(Ah + (size_t)(bm + lrow) * DM + lcol0);
    const char* gAl = (const char*)(Al + (size_t)(bm + lrow) * DM + lcol0);
    const char* gBh = (const char*)(Wh + (size_t)(bn + lrow) * DM + lcol0);
    const char* gBl = (const char*)(Wl + (size_t)(bn + lrow) * DM + lcol0);
    const uint32_t soff = (uint32_t)(lrow * SA + lcol0) * 2;

    auto load_chunk = [&](int c, int stg) {
        const uint32_t base = sb + stg * STAGEB;
        const int gb = c * BKC * 2;      // byte offset along K
        CP_ASYNC_16(base + 0 * TILEB + soff,      gAh + gb);
        CP_ASYNC_16(base + 0 * TILEB + soff + 16, gAh + gb + 16);
        CP_ASYNC_16(base + 1 * TILEB + soff,      gAl + gb);
        CP_ASYNC_16(base + 1 * TILEB + soff + 16, gAl + gb + 16);
        CP_ASYNC_16(base + 2 * TILEB + soff,      gBh + gb);
        CP_ASYNC_16(base + 2 * TILEB + soff + 16, gBh + gb + 16);
        CP_ASYNC_16(base + 3 * TILEB + soff,      gBl + gb);
        CP_ASYNC_16(base + 3 * TILEB + soff + 16, gBl + gb + 16);
        CP_ASYNC_COMMIT();
    };

    // ---- ldmatrix per-lane address components ----
    const int grp = lane >> 3, rin = lane & 7;
    // A x4: groups -> (m +8*(g&1), k +8*(g>>1))
    const int a_row = wm + (grp & 1) * 8 + rin;
    const int a_kof = (grp >> 1) * 8;
    // B x4 (two n8 tiles): groups -> (n +8*(g>>1), k +8*(g&1))
    const int b_row = wn + (grp >> 1) * 8 + rin;
    const int b_kof = (grp & 1) * 8;

    float acc[4][4][4];
#pragma unroll
    for (int i = 0; i < 4; i++)
#pragma unroll
        for (int j = 0; j < 4; j++)
#pragma unroll
            for (int r = 0; r < 4; r++) acc[i][j][r] = 0.0f;

    load_chunk(0, 0);

    for (int c = 0; c < NCH; c++) {
        if (c + 1 < NCH) {
            load_chunk(c + 1, (c + 1) & 1);
            CP_ASYNC_WAIT1();
        } else {
            CP_ASYNC_WAIT0();
        }
        __syncthreads();

        const uint32_t base = sb + (c & 1) * STAGEB;
#pragma unroll
        for (int k0 = 0; k0 < BKC; k0 += 16) {
            uint32_t ah[4][4], al[4][4], bh[4][2], bl[4][2];
#pragma unroll
            for (int i = 0; i < 4; i++) {
                uint32_t ad = base + 0 * TILEB +
                    (uint32_t)((a_row + i * 16) * SA + k0 + a_kof) * 2;
                ldsm_x4(ah[i][0], ah[i][1], ah[i][2], ah[i][3], ad);
                uint32_t ad2 = base + 1 * TILEB +
                    (uint32_t)((a_row + i * 16) * SA + k0 + a_kof) * 2;
                ldsm_x4(al[i][0], al[i][1], al[i][2], al[i][3], ad2);
            }
#pragma unroll
            for (int jp = 0; jp < 2; jp++) {     // n8-tile pairs (j=2jp, 2jp+1)
                uint32_t bd = base + 2 * TILEB +
                    (uint32_t)((b_row + jp * 16) * SA + k0 + b_kof) * 2;
                ldsm_x4(bh[jp * 2][0], bh[jp * 2][1],
                        bh[jp * 2 + 1][0], bh[jp * 2 + 1][1], bd);
                uint32_t bd2 = base + 3 * TILEB +
                    (uint32_t)((b_row + jp * 16) * SA + k0 + b_kof) * 2;
                ldsm_x4(bl[jp * 2][0], bl[jp * 2][1],
                        bl[jp * 2 + 1][0], bl[jp * 2 + 1][1], bd2);
            }
#pragma unroll
            for (int i = 0; i < 4; i++)
#pragma unroll
                for (int j = 0; j < 4; j++) {
                    mma_bf16(acc[i][j], ah[i], bh[j]);   // hi*hi
                    mma_bf16(acc[i][j], ah[i], bl[j]);   // hi*lo
                    mma_bf16(acc[i][j], al[i], bh[j]);   // lo*hi
                }
        }
        __syncthreads();
    }

    // ---- epilogue: c0,c1 -> (row, col..col+1); c2,c3 -> (row+8, ...) ----
    const int erow = bm + wm + (lane >> 2);
    const int ecol = bn + wn + (lane & 3) * 2;
#pragma unroll
    for (int i = 0; i < 4; i++) {
#pragma unroll
        for (int j = 0; j < 4; j++) {
            const int col = ecol + j * 8;
            const float b0 = bias[col], b1 = bias[col + 1];
            float* p0 = C + (size_t)(erow + i * 16) * DM + col;
            float* p1 = C + (size_t)(erow + i * 16 + 8) * DM + col;
            float2 v0 = make_float2(acc[i][j][0] + b0, acc[i][j][1] + b1);
            float2 v1 = make_float2(acc[i][j][2] + b0, acc[i][j][3] + b1);
            *(float2*)p0 = v0;
            *(float2*)p1 = v1;
        }
    }
}

// ---------------------------------------------------------------------------
// Flash attention, fp32 (unchanged, known-correct).
// ---------------------------------------------------------------------------
#define TP 68   // padded tile stride (64 + 4)

__global__ __launch_bounds__(256) void attn_kernel(
    const float* __restrict__ Q, const float* __restrict__ K,
    const float* __restrict__ V, float* __restrict__ X)
{
    extern __shared__ float sm[];
    float* Qs   = sm;
    float* Ks   = Qs + 64 * TP;
    float* Vs   = Ks + 64 * TP;
    float* Ps   = Vs + 64 * TP;
    float* rmax = Ps + 64 * TP;
    float* rsum = rmax + 64;

    const int tid = threadIdx.x;
    const int tx = tid & 15;
    const int ty = tid >> 4;
    const int qb = blockIdx.x;
    const int h  = blockIdx.y;
    const int b  = blockIdx.z;
    const size_t headbase = ((size_t)b * SS) * DM + (size_t)h * HD;

#pragma unroll
    for (int i = 0; i < 4; i++) {
        int f = tid + i * 256;
        int r = f >> 4, d4 = (f & 15) << 2;
        *(float4*)&Qs[r * TP + d4] =
            *(const float4*)&Q[headbase + (size_t)(qb * 64 + r) * DM + d4];
    }
    if (tid < 64) { rmax[tid] = -3.0e38f; rsum[tid] = 0.0f; }

    float o[4][4];
#pragma unroll
    for (int i = 0; i < 4; i++)
#pragma unroll
        for (int j = 0; j < 4; j++) o[i][j] = 0.0f;

    __syncthreads();

    const float inv_scale = 0.03125f;   // 1/sqrt(D) = 1/32

    for (int kt = 0; kt < SS / 64; kt++) {
#pragma unroll
        for (int i = 0; i < 4; i++) {
            int f = tid + i * 256;
            int r = f >> 4, d4 = (f & 15) << 2;
            size_t g = headbase + (size_t)(kt * 64 + r) * DM + d4;
            *(float4*)&Ks[r * TP + d4] = *(const float4*)&K[g];
            *(float4*)&Vs[r * TP + d4] = *(const float4*)&V[g];
        }
        __syncthreads();

        float s[4][4];
#pragma unroll
        for (int i = 0; i < 4; i++)
#pragma unroll
            for (int j = 0; j < 4; j++) s[i][j] = 0.0f;

#pragma unroll
        for (int d0 = 0; d0 < 64; d0 += 4) {
            float4 qv[4], kv[4];
#pragma unroll
            for (int i = 0; i < 4; i++)
                qv[i] = *(const float4*)&Qs[(ty * 4 + i) * TP + d0];
#pragma unroll
            for (int j = 0; j < 4; j++)
                kv[j] = *(const float4*)&Ks[(tx * 4 + j) * TP + d0];
#pragma unroll
            for (int i = 0; i < 4; i++)
#pragma unroll
                for (int j = 0; j < 4; j++)
                    s[i][j] += qv[i].x * kv[j].x + qv[i].y * kv[j].y +
                               qv[i].z * kv[j].z + qv[i].w * kv[j].w;
        }

#pragma unroll
        for (int i = 0; i < 4; i++) {
            int r = ty * 4 + i;
            float tmax = -3.0e38f;
#pragma unroll
            for (int j = 0; j < 4; j++) {
                s[i][j] *= inv_scale;
                tmax = fmaxf(tmax, s[i][j]);
            }
#pragma unroll
            for (int off = 8; off > 0; off >>= 1)
                tmax = fmaxf(tmax, __shfl_xor_sync(0xffffffffu, tmax, off));

            float mold = rmax[r];
            float mnew = fmaxf(mold, tmax);
            float factor = __expf(mold - mnew);

            float4 pv;
            pv.x = __expf(s[i][0] - mnew);
            pv.y = __expf(s[i][1] - mnew);
            pv.z = __expf(s[i][2] - mnew);
            pv.w = __expf(s[i][3] - mnew);
            float tsum = pv.x + pv.y + pv.z + pv.w;
#pragma unroll
            for (int off = 8; off > 0; off >>= 1)
                tsum += __shfl_xor_sync(0xffffffffu, tsum, off);

            *(float4*)&Ps[r * TP + tx * 4] = pv;
#pragma unroll
            for (int j = 0; j < 4; j++) o[i][j] *= factor;
            if (tx == 0) {
                rmax[r] = mnew;
                rsum[r] = rsum[r] * factor + tsum;
            }
        }
        __syncthreads();

#pragma unroll
        for (int c0 = 0; c0 < 64; c0 += 4) {
            float4 pr[4], vv[4];
#pragma unroll
            for (int i = 0; i < 4; i++)
                pr[i] = *(const float4*)&Ps[(ty * 4 + i) * TP + c0];
#pragma unroll
            for (int k = 0; k < 4; k++)
                vv[k] = *(const float4*)&Vs[(c0 + k) * TP + tx * 4];
#pragma unroll
            for (int i = 0; i < 4; i++) {
                o[i][0] += pr[i].x * vv[0].x + pr[i].y * vv[1].x +
                           pr[i].z * vv[2].x + pr[i].w * vv[3].x;
                o[i][1] += pr[i].x * vv[0].y + pr[i].y * vv[1].y +
                           pr[i].z * vv[2].y + pr[i].w * vv[3].y;
                o[i][2] += pr[i].x * vv[0].z + pr[i].y * vv[1].z +
                           pr[i].z * vv[2].z + pr[i].w * vv[3].z;
                o[i][3] += pr[i].x * vv[0].w + pr[i].y * vv[1].w +
                           pr[i].z * vv[2].w + pr[i].w * vv[3].w;
            }
        }
        __syncthreads();
    }

#pragma unroll
    for (int i = 0; i < 4; i++) {
        int r = ty * 4 + i;
        float inv = 1.0f / rsum[r];
        float4 ov;
        ov.x = o[i][0] * inv; ov.y = o[i][1] * inv;
        ov.z = o[i][2] * inv; ov.w = o[i][3] * inv;
        *(float4*)&X[headbase + (size_t)(qb * 64 + r) * DM + tx * 4] = ov;
    }
}

// ---------------------------------------------------------------------------
extern "C" void kernel_launch(void* const* d_in, const int* in_sizes, int n_in,
                              void* d_out, int out_size)
{
    const float* query = (const float*)d_in[0];
    const float* key   = (const float*)d_in[1];
    const float* value = (const float*)d_in[2];
    const float* Wq    = (const float*)d_in[3];
    const float* bq    = (const float*)d_in[4];
    const float* Wk    = (const float*)d_in[5];
    const float* bk    = (const float*)d_in[6];
    const float* Wv    = (const float*)d_in[7];
    const float* bv    = (const float*)d_in[8];
    const float* Wo    = (const float*)d_in[9];
    const float* bo    = (const float*)d_in[10];
    float* out = (float*)d_out;

    float *qp, *kp, *vp, *xp;
    __nv_bfloat16 *ah, *al, *wh, *wl;
    cudaGetSymbolAddress((void**)&qp, g_Q);
    cudaGetSymbolAddress((void**)&kp, g_K);
    cudaGetSymbolAddress((void**)&vp, g_V);
    cudaGetSymbolAddress((void**)&xp, g_X);
    cudaGetSymbolAddress((void**)&ah, g_Ah);
    cudaGetSymbolAddress((void**)&al, g_Al);
    cudaGetSymbolAddress((void**)&wh, g_Wh);
    cudaGetSymbolAddress((void**)&wl, g_Wl);

    cudaFuncSetAttribute(gemm_mma,
                         cudaFuncAttributeMaxDynamicSharedMemorySize, GEMM_SMEM);

    const int nA4 = MROWS * DM / 4;
    const int nW4 = DM * DM / 4;
    dim3 ggrid(DM / 128, MROWS / 128);   // (8, 64)

    // Q projection
    split_bf16_kernel<<<2048, 256>>>(query, ah, al, nA4);
    split_bf16_kernel<<<512, 256>>>(Wq, wh, wl, nW4);
    gemm_mma<<<ggrid, 256, GEMM_SMEM>>>(ah, al, wh, wl, bq, qp);
    // K projection
    split_bf16_kernel<<<2048, 256>>>(key, ah, al, nA4);
    split_bf16_kernel<<<512, 256>>>(Wk, wh, wl, nW4);
    gemm_mma<<<ggrid, 256, GEMM_SMEM>>>(ah, al, wh, wl, bk, kp);
    // V projection
    split_bf16_kernel<<<2048, 256>>>(value, ah, al, nA4);
    split_bf16_kernel<<<512, 256>>>(Wv, wh, wl, nW4);
    gemm_mma<<<ggrid, 256, GEMM_SMEM>>>(ah, al, wh, wl, bv, vp);

    // Attention (fp32)
    int smem_bytes = (4 * 64 * TP + 128) * (int)sizeof(float);   // ~70 KB
    cudaFuncSetAttribute(attn_kernel,
                         cudaFuncAttributeMaxDynamicSharedMemorySize, smem_bytes);
    attn_kernel<<<dim3(SS / 64, HH, BB), 256, smem_bytes>>>(qp, kp, vp, xp);

    // Output projection
    split_bf16_kernel<<<2048, 256>>>(xp, ah, al, nA4);
    split_bf16_kernel<<<512, 256>>>(Wo, wh, wl, nW4);
    gemm_mma<<<ggrid, 256, GEMM_SMEM>>>(ah, al, wh, wl, bo, out);
}

// round 5
// speedup vs baseline: 3.2813x; 2.7124x over previous
#include <cuda_runtime.h>
#include <cuda_bf16.h>
#include <cstdint>

// Problem constants
#define BB 4
#define SS 2048
#define DM 1024
#define HH 16
#define HD 64
#define MROWS (BB * SS)   // 8192

// Scratch (allocation-free rule: __device__ globals)
__device__ __nv_bfloat16 g_Ah[MROWS * DM];
__device__ __nv_bfloat16 g_Al[MROWS * DM];
__device__ __nv_bfloat16 g_Wh[DM * DM];
__device__ __nv_bfloat16 g_Wl[DM * DM];
__device__ __nv_bfloat16 g_Qh[MROWS * DM];
__device__ __nv_bfloat16 g_Ql[MROWS * DM];
__device__ __nv_bfloat16 g_Kh[MROWS * DM];
__device__ __nv_bfloat16 g_Kl[MROWS * DM];
__device__ __nv_bfloat16 g_Vh[MROWS * DM];
__device__ __nv_bfloat16 g_Vl[MROWS * DM];
__device__ __nv_bfloat16 g_Xh[MROWS * DM];
__device__ __nv_bfloat16 g_Xl[MROWS * DM];

// ---------------------------------------------------------------------------
// Portable (sm_80+) tensor-core helpers
// ---------------------------------------------------------------------------
__device__ __forceinline__ uint32_t smem_to_u32(const void* p) {
    uint32_t a;
    asm("{ .reg .u64 t; cvta.to.shared.u64 t, %1; cvt.u32.u64 %0, t; }"
        : "=r"(a) : "l"(p));
    return a;
}

__device__ __forceinline__ void ldsm_x4(uint32_t& r0, uint32_t& r1,
                                        uint32_t& r2, uint32_t& r3,
                                        uint32_t addr) {
    asm volatile("ldmatrix.sync.aligned.m8n8.x4.shared.b16 {%0,%1,%2,%3}, [%4];"
                 : "=r"(r0), "=r"(r1), "=r"(r2), "=r"(r3) : "r"(addr));
}

__device__ __forceinline__ void ldsm_x4_t(uint32_t& r0, uint32_t& r1,
                                          uint32_t& r2, uint32_t& r3,
                                          uint32_t addr) {
    asm volatile("ldmatrix.sync.aligned.m8n8.x4.trans.shared.b16 {%0,%1,%2,%3}, [%4];"
                 : "=r"(r0), "=r"(r1), "=r"(r2), "=r"(r3) : "r"(addr));
}

__device__ __forceinline__ void mma_bf16(float* c, const uint32_t* a,
                                         uint32_t b0, uint32_t b1) {
    asm volatile(
        "mma.sync.aligned.m16n8k16.row.col.f32.bf16.bf16.f32 "
        "{%0,%1,%2,%3}, {%4,%5,%6,%7}, {%8,%9}, {%0,%1,%2,%3};"
        : "+f"(c[0]), "+f"(c[1]), "+f"(c[2]), "+f"(c[3])
        : "r"(a[0]), "r"(a[1]), "r"(a[2]), "r"(a[3]), "r"(b0), "r"(b1));
}

#define CP_ASYNC_16(smem_u32, gptr) \
    asm volatile("cp.async.cg.shared.global [%0], [%1], 16;" \
        :: "r"(smem_u32), "l"(gptr) : "memory")
#define CP_ASYNC_COMMIT() asm volatile("cp.async.commit_group;" ::: "memory")
#define CP_ASYNC_WAIT1() asm volatile("cp.async.wait_group 1;" ::: "memory")
#define CP_ASYNC_WAIT0() asm volatile("cp.async.wait_group 0;" ::: "memory")

// x = hi + lo (bf16 pair), packed two-at-a-time into bf16x2 registers
__device__ __forceinline__ void split2(float x, float y, uint32_t& hi, uint32_t& lo) {
    __nv_bfloat16 hx = __float2bfloat16_rn(x);
    __nv_bfloat16 hy = __float2bfloat16_rn(y);
    __nv_bfloat16 lx = __float2bfloat16_rn(x - __bfloat162float(hx));
    __nv_bfloat16 ly = __float2bfloat16_rn(y - __bfloat162float(hy));
    hi = ((uint32_t)__bfloat16_as_ushort(hy) << 16) | __bfloat16_as_ushort(hx);
    lo = ((uint32_t)__bfloat16_as_ushort(ly) << 16) | __bfloat16_as_ushort(lx);
}

// ---------------------------------------------------------------------------
// Split fp32 -> (bf16 hi, bf16 lo)
// ---------------------------------------------------------------------------
__global__ __launch_bounds__(256) void split_bf16_kernel(
    const float* __restrict__ x, __nv_bfloat16* __restrict__ hi,
    __nv_bfloat16* __restrict__ lo, int n4)
{
    int i = blockIdx.x * blockDim.x + threadIdx.x;
    int stride = gridDim.x * blockDim.x;
    for (; i < n4; i += stride) {
        float4 v = ((const float4*)x)[i];
        uint32_t h0, l0, h1, l1;
        split2(v.x, v.y, h0, l0);
        split2(v.z, v.w, h1, l1);
        uint2 hv = make_uint2(h0, h1), lv = make_uint2(l0, l1);
        ((uint2*)hi)[i] = hv;
        ((uint2*)lo)[i] = lv;
    }
}

// ---------------------------------------------------------------------------
// HMMA GEMM: C = (Ah+Al) @ (Wh+Wl)^T + bias, 3-MMA split.
// SPLIT_OUT=false: write fp32 C.  SPLIT_OUT=true: write bf16 hi/lo pair.
// ---------------------------------------------------------------------------
#define SA    40
#define TILEB (128 * SA * 2)
#define STAGEB (4 * TILEB)
#define GEMM_SMEM (2 * STAGEB)           // 81920 B
#define BKC   32
#define NCH   (DM / BKC)

template <bool SPLIT_OUT>
__global__ __launch_bounds__(256, 1) void gemm_mma(
    const __nv_bfloat16* __restrict__ Ah, const __nv_bfloat16* __restrict__ Al,
    const __nv_bfloat16* __restrict__ Wh, const __nv_bfloat16* __restrict__ Wl,
    const float* __restrict__ bias, float* __restrict__ C,
    __nv_bfloat16* __restrict__ Ch, __nv_bfloat16* __restrict__ Cl)
{
    extern __shared__ char smem[];
    const uint32_t sb = smem_to_u32(smem);
    const int tid  = threadIdx.x;
    const int wid  = tid >> 5;
    const int lane = tid & 31;
    const int bm = blockIdx.y * 128;
    const int bn = blockIdx.x * 128;
    const int wm = (wid >> 2) * 64;
    const int wn = (wid & 3) * 32;

    const int lrow  = tid >> 1;
    const int lcol0 = (tid & 1) * 16;
    const char* gAh = (const char*)(Ah + (size_t)(bm + lrow) * DM + lcol0);
    const char* gAl = (const char*)(Al + (size_t)(bm + lrow) * DM + lcol0);
    const char* gBh = (const char*)(Wh + (size_t)(bn + lrow) * DM + lcol0);
    const char* gBl = (const char*)(Wl + (size_t)(bn + lrow) * DM + lcol0);
    const uint32_t soff = (uint32_t)(lrow * SA + lcol0) * 2;

    auto load_chunk = [&](int c, int stg) {
        const uint32_t base = sb + stg * STAGEB;
        const int gb = c * BKC * 2;
        CP_ASYNC_16(base + 0 * TILEB + soff,      gAh + gb);
        CP_ASYNC_16(base + 0 * TILEB + soff + 16, gAh + gb + 16);
        CP_ASYNC_16(base + 1 * TILEB + soff,      gAl + gb);
        CP_ASYNC_16(base + 1 * TILEB + soff + 16, gAl + gb + 16);
        CP_ASYNC_16(base + 2 * TILEB + soff,      gBh + gb);
        CP_ASYNC_16(base + 2 * TILEB + soff + 16, gBh + gb + 16);
        CP_ASYNC_16(base + 3 * TILEB + soff,      gBl + gb);
        CP_ASYNC_16(base + 3 * TILEB + soff + 16, gBl + gb + 16);
        CP_ASYNC_COMMIT();
    };

    const int grp = lane >> 3, rin = lane & 7;
    const int a_row = wm + (grp & 1) * 8 + rin;
    const int a_kof = (grp >> 1) * 8;
    const int b_row = wn + (grp >> 1) * 8 + rin;
    const int b_kof = (grp & 1) * 8;

    float acc[4][4][4];
#pragma unroll
    for (int i = 0; i < 4; i++)
#pragma unroll
        for (int j = 0; j < 4; j++)
#pragma unroll
            for (int r = 0; r < 4; r++) acc[i][j][r] = 0.0f;

    load_chunk(0, 0);

    for (int c = 0; c < NCH; c++) {
        if (c + 1 < NCH) {
            load_chunk(c + 1, (c + 1) & 1);
            CP_ASYNC_WAIT1();
        } else {
            CP_ASYNC_WAIT0();
        }
        __syncthreads();

        const uint32_t base = sb + (c & 1) * STAGEB;
#pragma unroll
        for (int k0 = 0; k0 < BKC; k0 += 16) {
            uint32_t ah[4][4], al[4][4], bh[4][2], bl[4][2];
#pragma unroll
            for (int i = 0; i < 4; i++) {
                uint32_t ad = base + 0 * TILEB +
                    (uint32_t)((a_row + i * 16) * SA + k0 + a_kof) * 2;
                ldsm_x4(ah[i][0], ah[i][1], ah[i][2], ah[i][3], ad);
                uint32_t ad2 = base + 1 * TILEB +
                    (uint32_t)((a_row + i * 16) * SA + k0 + a_kof) * 2;
                ldsm_x4(al[i][0], al[i][1], al[i][2], al[i][3], ad2);
            }
#pragma unroll
            for (int jp = 0; jp < 2; jp++) {
                uint32_t bd = base + 2 * TILEB +
                    (uint32_t)((b_row + jp * 16) * SA + k0 + b_kof) * 2;
                ldsm_x4(bh[jp * 2][0], bh[jp * 2][1],
                        bh[jp * 2 + 1][0], bh[jp * 2 + 1][1], bd);
                uint32_t bd2 = base + 3 * TILEB +
                    (uint32_t)((b_row + jp * 16) * SA + k0 + b_kof) * 2;
                ldsm_x4(bl[jp * 2][0], bl[jp * 2][1],
                        bl[jp * 2 + 1][0], bl[jp * 2 + 1][1], bd2);
            }
#pragma unroll
            for (int i = 0; i < 4; i++)
#pragma unroll
                for (int j = 0; j < 4; j++) {
                    mma_bf16(acc[i][j], ah[i], bh[j][0], bh[j][1]);
                    mma_bf16(acc[i][j], ah[i], bl[j][0], bl[j][1]);
                    mma_bf16(acc[i][j], al[i], bh[j][0], bh[j][1]);
                }
        }
        __syncthreads();
    }

    const int erow = bm + wm + (lane >> 2);
    const int ecol = bn + wn + (lane & 3) * 2;
#pragma unroll
    for (int i = 0; i < 4; i++) {
#pragma unroll
        for (int j = 0; j < 4; j++) {
            const int col = ecol + j * 8;
            const float b0 = bias[col], b1 = bias[col + 1];
            const size_t o0 = (size_t)(erow + i * 16) * DM + col;
            const size_t o1 = (size_t)(erow + i * 16 + 8) * DM + col;
            if (SPLIT_OUT) {
                uint32_t h, l;
                split2(acc[i][j][0] + b0, acc[i][j][1] + b1, h, l);
                *(uint32_t*)(Ch + o0) = h;
                *(uint32_t*)(Cl + o0) = l;
                split2(acc[i][j][2] + b0, acc[i][j][3] + b1, h, l);
                *(uint32_t*)(Ch + o1) = h;
                *(uint32_t*)(Cl + o1) = l;
            } else {
                *(float2*)(C + o0) =
                    make_float2(acc[i][j][0] + b0, acc[i][j][1] + b1);
                *(float2*)(C + o1) =
                    make_float2(acc[i][j][2] + b0, acc[i][j][3] + b1);
            }
        }
    }
}

// ---------------------------------------------------------------------------
// HMMA flash attention, bf16-split both GEMMs.
// Block: 128 queries x (h, b). 8 warps x 16 query rows, 128-key tiles.
// ---------------------------------------------------------------------------
#define ASA 72                      // smem stride (bf16), conflict-free ldmatrix
#define ATILE (128 * ASA * 2)       // 18432 B
#define A_QH 0
#define A_QL ATILE
#define A_ST0 (2 * ATILE)
#define A_STAGE (4 * ATILE)         // Kh, Kl, Vh, Vl
#define ATT_SMEM (2 * ATILE + 2 * A_STAGE)   // 184320 B
#define NKT (SS / 128)              // 16

__global__ __launch_bounds__(256, 1) void attn_mma(
    const __nv_bfloat16* __restrict__ Qh_, const __nv_bfloat16* __restrict__ Ql_,
    const __nv_bfloat16* __restrict__ Kh_, const __nv_bfloat16* __restrict__ Kl_,
    const __nv_bfloat16* __restrict__ Vh_, const __nv_bfloat16* __restrict__ Vl_,
    __nv_bfloat16* __restrict__ Xh_, __nv_bfloat16* __restrict__ Xl_)
{
    extern __shared__ char smem[];
    const uint32_t sb = smem_to_u32(smem);
    const int tid  = threadIdx.x;
    const int wid  = tid >> 5;
    const int lane = tid & 31;
    const int qm   = wid * 16;
    const int qb = blockIdx.x, h = blockIdx.y, b = blockIdx.z;
    const size_t qrow0 = (size_t)(b * SS + qb * 128);
    const size_t hoff  = (size_t)h * HD;

    // Q tile (hi+lo) via cp.async
#pragma unroll
    for (int i = 0; i < 4; i++) {
        int ci = tid + i * 256;
        int r = ci >> 3, cof = (ci & 7) * 16;
        uint32_t so = (uint32_t)(r * ASA * 2) + cof;
        CP_ASYNC_16(sb + A_QH + so,
                    (const char*)(Qh_ + (qrow0 + r) * DM + hoff) + cof);
        CP_ASYNC_16(sb + A_QL + so,
                    (const char*)(Ql_ + (qrow0 + r) * DM + hoff) + cof);
    }
    CP_ASYNC_COMMIT();

    auto load_kv = [&](int kt, int stg) {
        const size_t k0 = (size_t)(b * SS + kt * 128);
        const uint32_t base = sb + A_ST0 + stg * A_STAGE;
#pragma unroll
        for (int i = 0; i < 4; i++) {
            int ci = tid + i * 256;
            int r = ci >> 3, cof = (ci & 7) * 16;
            uint32_t so = (uint32_t)(r * ASA * 2) + cof;
            const size_t g = (k0 + r) * DM + hoff;
            CP_ASYNC_16(base + 0 * ATILE + so, (const char*)(Kh_ + g) + cof);
            CP_ASYNC_16(base + 1 * ATILE + so, (const char*)(Kl_ + g) + cof);
            CP_ASYNC_16(base + 2 * ATILE + so, (const char*)(Vh_ + g) + cof);
            CP_ASYNC_16(base + 3 * ATILE + so, (const char*)(Vl_ + g) + cof);
        }
        CP_ASYNC_COMMIT();
    };

    load_kv(0, 0);

    float O[8][4];
#pragma unroll
    for (int jo = 0; jo < 8; jo++)
#pragma unroll
        for (int r = 0; r < 4; r++) O[jo][r] = 0.0f;
    float M0 = -3.0e38f, M1 = -3.0e38f, L0 = 0.0f, L1 = 0.0f;
    const float inv = 0.03125f;   // 1/sqrt(D) = 1/32 (module scales by hid_dim)

    // ldmatrix lane address components
    const int qrow_f = qm + (lane & 7) + ((lane >> 3) & 1) * 8;   // A frag
    const int qkof_f = ((lane >> 4) & 1) * 8;
    const int krow_f = (lane & 7) + ((lane >> 4) & 1) * 8;        // B frag (K)
    const int kkof_f = ((lane >> 3) & 1) * 8;
    const int vrow_f = lane & 15;                                 // B frag (V, trans)
    const int vcol_f = (lane >> 4) * 8;

    for (int kt = 0; kt < NKT; kt++) {
        if (kt + 1 < NKT) {
            load_kv(kt + 1, (kt + 1) & 1);
            CP_ASYNC_WAIT1();
        } else {
            CP_ASYNC_WAIT0();
        }
        __syncthreads();
        const uint32_t stage = sb + A_ST0 + (kt & 1) * A_STAGE;

        // ---- S = Q @ K^T (3-MMA split) ----
        float s[16][4];
#pragma unroll
        for (int j = 0; j < 16; j++)
#pragma unroll
            for (int r = 0; r < 4; r++) s[j][r] = 0.0f;

#pragma unroll
        for (int ks = 0; ks < 4; ks++) {
            uint32_t qh[4], ql[4];
            uint32_t qa = sb + A_QH +
                (uint32_t)(qrow_f * ASA + qkof_f + ks * 16) * 2;
            ldsm_x4(qh[0], qh[1], qh[2], qh[3], qa);
            ldsm_x4(ql[0], ql[1], ql[2], ql[3], qa + ATILE);
#pragma unroll
            for (int jp = 0; jp < 8; jp++) {
                uint32_t kh[4], kl[4];
                uint32_t ka = stage + 0 * ATILE +
                    (uint32_t)((krow_f + jp * 16) * ASA + kkof_f + ks * 16) * 2;
                ldsm_x4(kh[0], kh[1], kh[2], kh[3], ka);
                ldsm_x4(kl[0], kl[1], kl[2], kl[3], ka + ATILE);
                mma_bf16(s[jp * 2],     qh, kh[0], kh[1]);
                mma_bf16(s[jp * 2],     qh, kl[0], kl[1]);
                mma_bf16(s[jp * 2],     ql, kh[0], kh[1]);
                mma_bf16(s[jp * 2 + 1], qh, kh[2], kh[3]);
                mma_bf16(s[jp * 2 + 1], qh, kl[2], kl[3]);
                mma_bf16(s[jp * 2 + 1], ql, kh[2], kh[3]);
            }
        }

        // ---- online softmax (registers + quad shuffles) ----
        float mx0 = -3.0e38f, mx1 = -3.0e38f;
#pragma unroll
        for (int j = 0; j < 16; j++) {
            mx0 = fmaxf(mx0, fmaxf(s[j][0], s[j][1]));
            mx1 = fmaxf(mx1, fmaxf(s[j][2], s[j][3]));
        }
        mx0 = fmaxf(mx0, __shfl_xor_sync(0xffffffffu, mx0, 1));
        mx0 = fmaxf(mx0, __shfl_xor_sync(0xffffffffu, mx0, 2));
        mx1 = fmaxf(mx1, __shfl_xor_sync(0xffffffffu, mx1, 1));
        mx1 = fmaxf(mx1, __shfl_xor_sync(0xffffffffu, mx1, 2));
        mx0 *= inv; mx1 *= inv;

        const float Mn0 = fmaxf(M0, mx0), Mn1 = fmaxf(M1, mx1);
        const float f0 = __expf(M0 - Mn0), f1 = __expf(M1 - Mn1);
        M0 = Mn0; M1 = Mn1;

        float sum0 = 0.0f, sum1 = 0.0f;
#pragma unroll
        for (int j = 0; j < 16; j++) {
            s[j][0] = __expf(s[j][0] * inv - M0);
            s[j][1] = __expf(s[j][1] * inv - M0);
            s[j][2] = __expf(s[j][2] * inv - M1);
            s[j][3] = __expf(s[j][3] * inv - M1);
            sum0 += s[j][0] + s[j][1];
            sum1 += s[j][2] + s[j][3];
        }
        sum0 += __shfl_xor_sync(0xffffffffu, sum0, 1);
        sum0 += __shfl_xor_sync(0xffffffffu, sum0, 2);
        sum1 += __shfl_xor_sync(0xffffffffu, sum1, 1);
        sum1 += __shfl_xor_sync(0xffffffffu, sum1, 2);
        L0 = L0 * f0 + sum0;
        L1 = L1 * f1 + sum1;

#pragma unroll
        for (int jo = 0; jo < 8; jo++) {
            O[jo][0] *= f0; O[jo][1] *= f0;
            O[jo][2] *= f1; O[jo][3] *= f1;
        }

        // ---- O += P @ V (3-MMA split; P fragments built in registers) ----
#pragma unroll
        for (int ks2 = 0; ks2 < 8; ks2++) {
            uint32_t ah[4], al[4];
            split2(s[2 * ks2][0],     s[2 * ks2][1],     ah[0], al[0]);
            split2(s[2 * ks2][2],     s[2 * ks2][3],     ah[1], al[1]);
            split2(s[2 * ks2 + 1][0], s[2 * ks2 + 1][1], ah[2], al[2]);
            split2(s[2 * ks2 + 1][2], s[2 * ks2 + 1][3], ah[3], al[3]);
#pragma unroll
            for (int nn = 0; nn < 4; nn++) {
                uint32_t vh[4], vl[4];
                uint32_t va = stage + 2 * ATILE +
                    (uint32_t)((ks2 * 16 + vrow_f) * ASA + nn * 16 + vcol_f) * 2;
                ldsm_x4_t(vh[0], vh[1], vh[2], vh[3], va);
                ldsm_x4_t(vl[0], vl[1], vl[2], vl[3], va + ATILE);
                mma_bf16(O[nn * 2],     ah, vh[0], vh[1]);
                mma_bf16(O[nn * 2],     ah, vl[0], vl[1]);
                mma_bf16(O[nn * 2],     al, vh[0], vh[1]);
                mma_bf16(O[nn * 2 + 1], ah, vh[2], vh[3]);
                mma_bf16(O[nn * 2 + 1], ah, vl[2], vl[3]);
                mma_bf16(O[nn * 2 + 1], al, vh[2], vh[3]);
            }
        }
        __syncthreads();
    }

    // ---- epilogue: normalize, split to bf16 hi/lo, store ----
    const float il0 = 1.0f / L0, il1 = 1.0f / L1;
    const size_t r0 = qrow0 + qm + (lane >> 2);
    const size_t r1 = r0 + 8;
#pragma unroll
    for (int jo = 0; jo < 8; jo++) {
        const size_t col = hoff + jo * 8 + (lane & 3) * 2;
        uint32_t hp, lp;
        split2(O[jo][0] * il0, O[jo][1] * il0, hp, lp);
        *(uint32_t*)(Xh_ + r0 * DM + col) = hp;
        *(uint32_t*)(Xl_ + r0 * DM + col) = lp;
        split2(O[jo][2] * il1, O[jo][3] * il1, hp, lp);
        *(uint32_t*)(Xh_ + r1 * DM + col) = hp;
        *(uint32_t*)(Xl_ + r1 * DM + col) = lp;
    }
}

// ---------------------------------------------------------------------------
extern "C" void kernel_launch(void* const* d_in, const int* in_sizes, int n_in,
                              void* d_out, int out_size)
{
    const float* query = (const float*)d_in[0];
    const float* key   = (const float*)d_in[1];
    const float* value = (const float*)d_in[2];
    const float* Wq    = (const float*)d_in[3];
    const float* bq    = (const float*)d_in[4];
    const float* Wk    = (const float*)d_in[5];
    const float* bk    = (const float*)d_in[6];
    const float* Wv    = (const float*)d_in[7];
    const float* bv    = (const float*)d_in[8];
    const float* Wo    = (const float*)d_in[9];
    const float* bo    = (const float*)d_in[10];
    float* out = (float*)d_out;

    __nv_bfloat16 *ah, *al, *wh, *wl, *qh, *ql, *kh, *kl, *vh, *vl, *xh, *xl;
    cudaGetSymbolAddress((void**)&ah, g_Ah);
    cudaGetSymbolAddress((void**)&al, g_Al);
    cudaGetSymbolAddress((void**)&wh, g_Wh);
    cudaGetSymbolAddress((void**)&wl, g_Wl);
    cudaGetSymbolAddress((void**)&qh, g_Qh);
    cudaGetSymbolAddress((void**)&ql, g_Ql);
    cudaGetSymbolAddress((void**)&kh, g_Kh);
    cudaGetSymbolAddress((void**)&kl, g_Kl);
    cudaGetSymbolAddress((void**)&vh, g_Vh);
    cudaGetSymbolAddress((void**)&vl, g_Vl);
    cudaGetSymbolAddress((void**)&xh, g_Xh);
    cudaGetSymbolAddress((void**)&xl, g_Xl);

    cudaFuncSetAttribute(gemm_mma<false>,
                         cudaFuncAttributeMaxDynamicSharedMemorySize, GEMM_SMEM);
    cudaFuncSetAttribute(gemm_mma<true>,
                         cudaFuncAttributeMaxDynamicSharedMemorySize, GEMM_SMEM);
    cudaFuncSetAttribute(attn_mma,
                         cudaFuncAttributeMaxDynamicSharedMemorySize, ATT_SMEM);

    const int nA4 = MROWS * DM / 4;
    const int nW4 = DM * DM / 4;
    dim3 ggrid(DM / 128, MROWS / 128);

    // Q projection -> bf16 hi/lo
    split_bf16_kernel<<<2048, 256>>>(query, ah, al, nA4);
    split_bf16_kernel<<<512, 256>>>(Wq, wh, wl, nW4);
    gemm_mma<true><<<ggrid, 256, GEMM_SMEM>>>(ah, al, wh, wl, bq,
                                              nullptr, qh, ql);
    // K projection
    split_bf16_kernel<<<2048, 256>>>(key, ah, al, nA4);
    split_bf16_kernel<<<512, 256>>>(Wk, wh, wl, nW4);
    gemm_mma<true><<<ggrid, 256, GEMM_SMEM>>>(ah, al, wh, wl, bk,
                                              nullptr, kh, kl);
    // V projection
    split_bf16_kernel<<<2048, 256>>>(value, ah, al, nA4);
    split_bf16_kernel<<<512, 256>>>(Wv, wh, wl, nW4);
    gemm_mma<true><<<ggrid, 256, GEMM_SMEM>>>(ah, al, wh, wl, bv,
                                              nullptr, vh, vl);

    // Attention (HMMA, bf16-split)
    attn_mma<<<dim3(SS / 128, HH, BB), 256, ATT_SMEM>>>(qh, ql, kh, kl,
                                                        vh, vl, xh, xl);

    // Output projection (fp32 out)
    split_bf16_kernel<<<512, 256>>>(Wo, wh, wl, nW4);
    gemm_mma<false><<<ggrid, 256, GEMM_SMEM>>>(xh, xl, wh, wl, bo,
                                               out, nullptr, nullptr);
}

// round 6
// speedup vs baseline: 3.3611x; 1.0243x over previous
#include <cuda_runtime.h>
#include <cuda_bf16.h>
#include <cstdint>

// Problem constants
#define BB 4
#define SS 2048
#define DM 1024
#define HH 16
#define HD 64
#define MROWS (BB * SS)   // 8192

// Scratch (allocation-free rule: __device__ globals)
__device__ __nv_bfloat16 g_Aqh[MROWS * DM], g_Aql[MROWS * DM];   // split(query)
__device__ __nv_bfloat16 g_Akh[MROWS * DM], g_Akl[MROWS * DM];   // split(key)
__device__ __nv_bfloat16 g_Avh[MROWS * DM], g_Avl[MROWS * DM];   // split(value)
__device__ __nv_bfloat16 g_Wqh[DM * DM], g_Wql[DM * DM];
__device__ __nv_bfloat16 g_Wkh[DM * DM], g_Wkl[DM * DM];
__device__ __nv_bfloat16 g_Wvh[DM * DM], g_Wvl[DM * DM];
__device__ __nv_bfloat16 g_Woh[DM * DM], g_Wol[DM * DM];
__device__ __nv_bfloat16 g_Qh[MROWS * DM], g_Ql[MROWS * DM];
__device__ __nv_bfloat16 g_Kh[MROWS * DM], g_Kl[MROWS * DM];
__device__ __nv_bfloat16 g_Vh[MROWS * DM], g_Vl[MROWS * DM];
__device__ __nv_bfloat16 g_Xh[MROWS * DM], g_Xl[MROWS * DM];

// ---------------------------------------------------------------------------
// Portable (sm_80+) tensor-core helpers
// ---------------------------------------------------------------------------
__device__ __forceinline__ uint32_t smem_to_u32(const void* p) {
    uint32_t a;
    asm("{ .reg .u64 t; cvta.to.shared.u64 t, %1; cvt.u32.u64 %0, t; }"
        : "=r"(a) : "l"(p));
    return a;
}

__device__ __forceinline__ void ldsm_x4(uint32_t& r0, uint32_t& r1,
                                        uint32_t& r2, uint32_t& r3,
                                        uint32_t addr) {
    asm volatile("ldmatrix.sync.aligned.m8n8.x4.shared.b16 {%0,%1,%2,%3}, [%4];"
                 : "=r"(r0), "=r"(r1), "=r"(r2), "=r"(r3) : "r"(addr));
}

__device__ __forceinline__ void ldsm_x4_t(uint32_t& r0, uint32_t& r1,
                                          uint32_t& r2, uint32_t& r3,
                                          uint32_t addr) {
    asm volatile("ldmatrix.sync.aligned.m8n8.x4.trans.shared.b16 {%0,%1,%2,%3}, [%4];"
                 : "=r"(r0), "=r"(r1), "=r"(r2), "=r"(r3) : "r"(addr));
}

__device__ __forceinline__ void mma_bf16(float* c, const uint32_t* a,
                                         uint32_t b0, uint32_t b1) {
    asm volatile(
        "mma.sync.aligned.m16n8k16.row.col.f32.bf16.bf16.f32 "
        "{%0,%1,%2,%3}, {%4,%5,%6,%7}, {%8,%9}, {%0,%1,%2,%3};"
        : "+f"(c[0]), "+f"(c[1]), "+f"(c[2]), "+f"(c[3])
        : "r"(a[0]), "r"(a[1]), "r"(a[2]), "r"(a[3]), "r"(b0), "r"(b1));
}

#define CP_ASYNC_16(smem_u32, gptr) \
    asm volatile("cp.async.cg.shared.global [%0], [%1], 16;" \
        :: "r"(smem_u32), "l"(gptr) : "memory")
#define CP_ASYNC_COMMIT() asm volatile("cp.async.commit_group;" ::: "memory")
#define CP_ASYNC_WAIT1() asm volatile("cp.async.wait_group 1;" ::: "memory")
#define CP_ASYNC_WAIT0() asm volatile("cp.async.wait_group 0;" ::: "memory")

// x = hi + lo (bf16 pair), packed two-at-a-time into bf16x2 registers
__device__ __forceinline__ void split2(float x, float y, uint32_t& hi, uint32_t& lo) {
    __nv_bfloat16 hx = __float2bfloat16_rn(x);
    __nv_bfloat16 hy = __float2bfloat16_rn(y);
    __nv_bfloat16 lx = __float2bfloat16_rn(x - __bfloat162float(hx));
    __nv_bfloat16 ly = __float2bfloat16_rn(y - __bfloat162float(hy));
    hi = ((uint32_t)__bfloat16_as_ushort(hy) << 16) | __bfloat16_as_ushort(hx);
    lo = ((uint32_t)__bfloat16_as_ushort(ly) << 16) | __bfloat16_as_ushort(lx);
}

__device__ __forceinline__ void split_body(const float* __restrict__ x,
                                           __nv_bfloat16* __restrict__ hi,
                                           __nv_bfloat16* __restrict__ lo, int n4)
{
    int i = blockIdx.x * blockDim.x + threadIdx.x;
    int stride = gridDim.x * blockDim.x;
    for (; i < n4; i += stride) {
        float4 v = ((const float4*)x)[i];
        uint32_t h0, l0, h1, l1;
        split2(v.x, v.y, h0, l0);
        split2(v.z, v.w, h1, l1);
        ((uint2*)hi)[i] = make_uint2(h0, h1);
        ((uint2*)lo)[i] = make_uint2(l0, l1);
    }
}

// Fused splits: inputs (z=0,1,2) and weights (z=0..3)
__global__ __launch_bounds__(256) void split_inputs_kernel(
    const float* __restrict__ q, const float* __restrict__ k,
    const float* __restrict__ v)
{
    const int n4 = MROWS * DM / 4;
    if (blockIdx.z == 0)      split_body(q, g_Aqh, g_Aql, n4);
    else if (blockIdx.z == 1) split_body(k, g_Akh, g_Akl, n4);
    else                      split_body(v, g_Avh, g_Avl, n4);
}

__global__ __launch_bounds__(256) void split_weights_kernel(
    const float* __restrict__ wq, const float* __restrict__ wk,
    const float* __restrict__ wv, const float* __restrict__ wo)
{
    const int n4 = DM * DM / 4;
    if (blockIdx.z == 0)      split_body(wq, g_Wqh, g_Wql, n4);
    else if (blockIdx.z == 1) split_body(wk, g_Wkh, g_Wkl, n4);
    else if (blockIdx.z == 2) split_body(wv, g_Wvh, g_Wvl, n4);
    else                      split_body(wo, g_Woh, g_Wol, n4);
}

// ---------------------------------------------------------------------------
// HMMA GEMM body: C = (Ah+Al) @ (Wh+Wl)^T + bias, 3-MMA split.
// 128x128 block tile; 8 warps x 64x32; BK=64; 3-stage cp.async pipeline;
// single __syncthreads per chunk.
// ---------------------------------------------------------------------------
#define SA2   72                          // smem row stride (bf16): conflict-free
#define TILE2 (128 * SA2 * 2)             // 18432 B per 128x64 tile
#define STG2  (4 * TILE2)                 // Ah, Al, Bh, Bl = 73728 B
#define GEMM_SMEM2 (3 * STG2)             // 221184 B
#define BKC2  64
#define NCH2  (DM / BKC2)                 // 16

template <bool SPLIT_OUT>
__device__ __forceinline__ void gemm64_body(
    const __nv_bfloat16* __restrict__ Ah, const __nv_bfloat16* __restrict__ Al,
    const __nv_bfloat16* __restrict__ Wh, const __nv_bfloat16* __restrict__ Wl,
    const float* __restrict__ bias, float* __restrict__ C,
    __nv_bfloat16* __restrict__ Ch, __nv_bfloat16* __restrict__ Cl)
{
    extern __shared__ char smem[];
    const uint32_t sb = smem_to_u32(smem);
    const int tid  = threadIdx.x;
    const int wid  = tid >> 5;
    const int lane = tid & 31;
    const int bm = blockIdx.y * 128;
    const int bn = blockIdx.x * 128;
    const int wm = (wid >> 2) * 64;
    const int wn = (wid & 3) * 32;

    // loader: thread -> (row, 64B half of the 128B row-chunk)
    const int lrow  = tid >> 1;
    const int lcolb = (tid & 1) * 64;     // byte offset in row chunk
    const char* gAh = (const char*)(Ah + (size_t)(bm + lrow) * DM) + lcolb;
    const char* gAl = (const char*)(Al + (size_t)(bm + lrow) * DM) + lcolb;
    const char* gBh = (const char*)(Wh + (size_t)(bn + lrow) * DM) + lcolb;
    const char* gBl = (const char*)(Wl + (size_t)(bn + lrow) * DM) + lcolb;
    const uint32_t so = (uint32_t)(lrow * SA2 * 2) + lcolb;

    auto load_chunk = [&](int c, int stg) {
        const uint32_t base = sb + stg * STG2;
        const int gb = c * (BKC2 * 2);
#pragma unroll
        for (int s = 0; s < 4; s++) {
            CP_ASYNC_16(base + 0 * TILE2 + so + s * 16, gAh + gb + s * 16);
            CP_ASYNC_16(base + 1 * TILE2 + so + s * 16, gAl + gb + s * 16);
            CP_ASYNC_16(base + 2 * TILE2 + so + s * 16, gBh + gb + s * 16);
            CP_ASYNC_16(base + 3 * TILE2 + so + s * 16, gBl + gb + s * 16);
        }
        CP_ASYNC_COMMIT();
    };

    const int grp = lane >> 3, rin = lane & 7;
    const int a_row = wm + (grp & 1) * 8 + rin;
    const int a_kof = (grp >> 1) * 8;
    const int b_row = wn + (grp >> 1) * 8 + rin;
    const int b_kof = (grp & 1) * 8;

    float acc[4][4][4];
#pragma unroll
    for (int i = 0; i < 4; i++)
#pragma unroll
        for (int j = 0; j < 4; j++)
#pragma unroll
            for (int r = 0; r < 4; r++) acc[i][j][r] = 0.0f;

    load_chunk(0, 0);
    load_chunk(1, 1);

    for (int c = 0; c < NCH2; c++) {
        if (c + 1 < NCH2) CP_ASYNC_WAIT1();
        else              CP_ASYNC_WAIT0();
        __syncthreads();                       // chunk c ready; stage (c+2)%3 free
        if (c + 2 < NCH2) load_chunk(c + 2, (c + 2) % 3);

        const uint32_t base = sb + (c % 3) * STG2;
#pragma unroll
        for (int k0 = 0; k0 < BKC2; k0 += 16) {
            uint32_t ah[4][4], al[4][4], bh[4][2], bl[4][2];
#pragma unroll
            for (int i = 0; i < 4; i++) {
                uint32_t ad = base + 0 * TILE2 +
                    (uint32_t)((a_row + i * 16) * SA2 + k0 + a_kof) * 2;
                ldsm_x4(ah[i][0], ah[i][1], ah[i][2], ah[i][3], ad);
                ldsm_x4(al[i][0], al[i][1], al[i][2], al[i][3], ad + TILE2);
            }
#pragma unroll
            for (int jp = 0; jp < 2; jp++) {
                uint32_t bd = base + 2 * TILE2 +
                    (uint32_t)((b_row + jp * 16) * SA2 + k0 + b_kof) * 2;
                ldsm_x4(bh[jp * 2][0], bh[jp * 2][1],
                        bh[jp * 2 + 1][0], bh[jp * 2 + 1][1], bd);
                ldsm_x4(bl[jp * 2][0], bl[jp * 2][1],
                        bl[jp * 2 + 1][0], bl[jp * 2 + 1][1], bd + TILE2);
            }
#pragma unroll
            for (int i = 0; i < 4; i++)
#pragma unroll
                for (int j = 0; j < 4; j++) {
                    mma_bf16(acc[i][j], ah[i], bh[j][0], bh[j][1]);
                    mma_bf16(acc[i][j], ah[i], bl[j][0], bl[j][1]);
                    mma_bf16(acc[i][j], al[i], bh[j][0], bh[j][1]);
                }
        }
    }

    const int erow = bm + wm + (lane >> 2);
    const int ecol = bn + wn + (lane & 3) * 2;
#pragma unroll
    for (int i = 0; i < 4; i++) {
#pragma unroll
        for (int j = 0; j < 4; j++) {
            const int col = ecol + j * 8;
            const float b0 = bias[col], b1 = bias[col + 1];
            const size_t o0 = (size_t)(erow + i * 16) * DM + col;
            const size_t o1 = (size_t)(erow + i * 16 + 8) * DM + col;
            if (SPLIT_OUT) {
                uint32_t hv, lv;
                split2(acc[i][j][0] + b0, acc[i][j][1] + b1, hv, lv);
                *(uint32_t*)(Ch + o0) = hv;
                *(uint32_t*)(Cl + o0) = lv;
                split2(acc[i][j][2] + b0, acc[i][j][3] + b1, hv, lv);
                *(uint32_t*)(Ch + o1) = hv;
                *(uint32_t*)(Cl + o1) = lv;
            } else {
                *(float2*)(C + o0) =
                    make_float2(acc[i][j][0] + b0, acc[i][j][1] + b1);
                *(float2*)(C + o1) =
                    make_float2(acc[i][j][2] + b0, acc[i][j][3] + b1);
            }
        }
    }
}

// Fused QKV projections: blockIdx.z selects {query,key,value} stream.
__global__ __launch_bounds__(256, 1) void qkv_gemm64(
    const float* __restrict__ bq, const float* __restrict__ bk,
    const float* __restrict__ bv)
{
    if (blockIdx.z == 0)
        gemm64_body<true>(g_Aqh, g_Aql, g_Wqh, g_Wql, bq, nullptr, g_Qh, g_Ql);
    else if (blockIdx.z == 1)
        gemm64_body<true>(g_Akh, g_Akl, g_Wkh, g_Wkl, bk, nullptr, g_Kh, g_Kl);
    else
        gemm64_body<true>(g_Avh, g_Avl, g_Wvh, g_Wvl, bv, nullptr, g_Vh, g_Vl);
}

// Output projection: fp32 out.
__global__ __launch_bounds__(256, 1) void out_gemm64(
    const float* __restrict__ bo, float* __restrict__ out)
{
    gemm64_body<false>(g_Xh, g_Xl, g_Woh, g_Wol, bo, out, nullptr, nullptr);
}

// ---------------------------------------------------------------------------
// HMMA flash attention, bf16-split both GEMMs (unchanged from round 5).
// ---------------------------------------------------------------------------
#define ASA 72
#define ATILE (128 * ASA * 2)
#define A_QH 0
#define A_QL ATILE
#define A_ST0 (2 * ATILE)
#define A_STAGE (4 * ATILE)
#define ATT_SMEM (2 * ATILE + 2 * A_STAGE)   // 184320 B
#define NKT (SS / 128)

__global__ __launch_bounds__(256, 1) void attn_mma(
    const __nv_bfloat16* __restrict__ Qh_, const __nv_bfloat16* __restrict__ Ql_,
    const __nv_bfloat16* __restrict__ Kh_, const __nv_bfloat16* __restrict__ Kl_,
    const __nv_bfloat16* __restrict__ Vh_, const __nv_bfloat16* __restrict__ Vl_,
    __nv_bfloat16* __restrict__ Xh_, __nv_bfloat16* __restrict__ Xl_)
{
    extern __shared__ char smem[];
    const uint32_t sb = smem_to_u32(smem);
    const int tid  = threadIdx.x;
    const int wid  = tid >> 5;
    const int lane = tid & 31;
    const int qm   = wid * 16;
    const int qb = blockIdx.x, h = blockIdx.y, b = blockIdx.z;
    const size_t qrow0 = (size_t)(b * SS + qb * 128);
    const size_t hoff  = (size_t)h * HD;

#pragma unroll
    for (int i = 0; i < 4; i++) {
        int ci = tid + i * 256;
        int r = ci >> 3, cof = (ci & 7) * 16;
        uint32_t so = (uint32_t)(r * ASA * 2) + cof;
        CP_ASYNC_16(sb + A_QH + so,
                    (const char*)(Qh_ + (qrow0 + r) * DM + hoff) + cof);
        CP_ASYNC_16(sb + A_QL + so,
                    (const char*)(Ql_ + (qrow0 + r) * DM + hoff) + cof);
    }
    CP_ASYNC_COMMIT();

    auto load_kv = [&](int kt, int stg) {
        const size_t k0 = (size_t)(b * SS + kt * 128);
        const uint32_t base = sb + A_ST0 + stg * A_STAGE;
#pragma unroll
        for (int i = 0; i < 4; i++) {
            int ci = tid + i * 256;
            int r = ci >> 3, cof = (ci & 7) * 16;
            uint32_t so = (uint32_t)(r * ASA * 2) + cof;
            const size_t g = (k0 + r) * DM + hoff;
            CP_ASYNC_16(base + 0 * ATILE + so, (const char*)(Kh_ + g) + cof);
            CP_ASYNC_16(base + 1 * ATILE + so, (const char*)(Kl_ + g) + cof);
            CP_ASYNC_16(base + 2 * ATILE + so, (const char*)(Vh_ + g) + cof);
            CP_ASYNC_16(base + 3 * ATILE + so, (const char*)(Vl_ + g) + cof);
        }
        CP_ASYNC_COMMIT();
    };

    load_kv(0, 0);

    float O[8][4];
#pragma unroll
    for (int jo = 0; jo < 8; jo++)
#pragma unroll
        for (int r = 0; r < 4; r++) O[jo][r] = 0.0f;
    float M0 = -3.0e38f, M1 = -3.0e38f, L0 = 0.0f, L1 = 0.0f;
    const float inv = 0.03125f;   // 1/sqrt(D) = 1/32 (module scales by hid_dim)

    const int qrow_f = qm + (lane & 7) + ((lane >> 3) & 1) * 8;
    const int qkof_f = ((lane >> 4) & 1) * 8;
    const int krow_f = (lane & 7) + ((lane >> 4) & 1) * 8;
    const int kkof_f = ((lane >> 3) & 1) * 8;
    const int vrow_f = lane & 15;
    const int vcol_f = (lane >> 4) * 8;

    for (int kt = 0; kt < NKT; kt++) {
        if (kt + 1 < NKT) {
            load_kv(kt + 1, (kt + 1) & 1);
            CP_ASYNC_WAIT1();
        } else {
            CP_ASYNC_WAIT0();
        }
        __syncthreads();
        const uint32_t stage = sb + A_ST0 + (kt & 1) * A_STAGE;

        float s[16][4];
#pragma unroll
        for (int j = 0; j < 16; j++)
#pragma unroll
            for (int r = 0; r < 4; r++) s[j][r] = 0.0f;

#pragma unroll
        for (int ks = 0; ks < 4; ks++) {
            uint32_t qh[4], ql[4];
            uint32_t qa = sb + A_QH +
                (uint32_t)(qrow_f * ASA + qkof_f + ks * 16) * 2;
            ldsm_x4(qh[0], qh[1], qh[2], qh[3], qa);
            ldsm_x4(ql[0], ql[1], ql[2], ql[3], qa + ATILE);
#pragma unroll
            for (int jp = 0; jp < 8; jp++) {
                uint32_t kh[4], kl[4];
                uint32_t ka = stage + 0 * ATILE +
                    (uint32_t)((krow_f + jp * 16) * ASA + kkof_f + ks * 16) * 2;
                ldsm_x4(kh[0], kh[1], kh[2], kh[3], ka);
                ldsm_x4(kl[0], kl[1], kl[2], kl[3], ka + ATILE);
                mma_bf16(s[jp * 2],     qh, kh[0], kh[1]);
                mma_bf16(s[jp * 2],     qh, kl[0], kl[1]);
                mma_bf16(s[jp * 2],     ql, kh[0], kh[1]);
                mma_bf16(s[jp * 2 + 1], qh, kh[2], kh[3]);
                mma_bf16(s[jp * 2 + 1], qh, kl[2], kl[3]);
                mma_bf16(s[jp * 2 + 1], ql, kh[2], kh[3]);
            }
        }

        float mx0 = -3.0e38f, mx1 = -3.0e38f;
#pragma unroll
        for (int j = 0; j < 16; j++) {
            mx0 = fmaxf(mx0, fmaxf(s[j][0], s[j][1]));
            mx1 = fmaxf(mx1, fmaxf(s[j][2], s[j][3]));
        }
        mx0 = fmaxf(mx0, __shfl_xor_sync(0xffffffffu, mx0, 1));
        mx0 = fmaxf(mx0, __shfl_xor_sync(0xffffffffu, mx0, 2));
        mx1 = fmaxf(mx1, __shfl_xor_sync(0xffffffffu, mx1, 1));
        mx1 = fmaxf(mx1, __shfl_xor_sync(0xffffffffu, mx1, 2));
        mx0 *= inv; mx1 *= inv;

        const float Mn0 = fmaxf(M0, mx0), Mn1 = fmaxf(M1, mx1);
        const float f0 = __expf(M0 - Mn0), f1 = __expf(M1 - Mn1);
        M0 = Mn0; M1 = Mn1;

        float sum0 = 0.0f, sum1 = 0.0f;
#pragma unroll
        for (int j = 0; j < 16; j++) {
            s[j][0] = __expf(s[j][0] * inv - M0);
            s[j][1] = __expf(s[j][1] * inv - M0);
            s[j][2] = __expf(s[j][2] * inv - M1);
            s[j][3] = __expf(s[j][3] * inv - M1);
            sum0 += s[j][0] + s[j][1];
            sum1 += s[j][2] + s[j][3];
        }
        sum0 += __shfl_xor_sync(0xffffffffu, sum0, 1);
        sum0 += __shfl_xor_sync(0xffffffffu, sum0, 2);
        sum1 += __shfl_xor_sync(0xffffffffu, sum1, 1);
        sum1 += __shfl_xor_sync(0xffffffffu, sum1, 2);
        L0 = L0 * f0 + sum0;
        L1 = L1 * f1 + sum1;

#pragma unroll
        for (int jo = 0; jo < 8; jo++) {
            O[jo][0] *= f0; O[jo][1] *= f0;
            O[jo][2] *= f1; O[jo][3] *= f1;
        }

#pragma unroll
        for (int ks2 = 0; ks2 < 8; ks2++) {
            uint32_t ah[4], al[4];
            split2(s[2 * ks2][0],     s[2 * ks2][1],     ah[0], al[0]);
            split2(s[2 * ks2][2],     s[2 * ks2][3],     ah[1], al[1]);
            split2(s[2 * ks2 + 1][0], s[2 * ks2 + 1][1], ah[2], al[2]);
            split2(s[2 * ks2 + 1][2], s[2 * ks2 + 1][3], ah[3], al[3]);
#pragma unroll
            for (int nn = 0; nn < 4; nn++) {
                uint32_t vh[4], vl[4];
                uint32_t va = stage + 2 * ATILE +
                    (uint32_t)((ks2 * 16 + vrow_f) * ASA + nn * 16 + vcol_f) * 2;
                ldsm_x4_t(vh[0], vh[1], vh[2], vh[3], va);
                ldsm_x4_t(vl[0], vl[1], vl[2], vl[3], va + ATILE);
                mma_bf16(O[nn * 2],     ah, vh[0], vh[1]);
                mma_bf16(O[nn * 2],     ah, vl[0], vl[1]);
                mma_bf16(O[nn * 2],     al, vh[0], vh[1]);
                mma_bf16(O[nn * 2 + 1], ah, vh[2], vh[3]);
                mma_bf16(O[nn * 2 + 1], ah, vl[2], vl[3]);
                mma_bf16(O[nn * 2 + 1], al, vh[2], vh[3]);
            }
        }
        __syncthreads();
    }

    const float il0 = 1.0f / L0, il1 = 1.0f / L1;
    const size_t r0 = qrow0 + qm + (lane >> 2);
    const size_t r1 = r0 + 8;
#pragma unroll
    for (int jo = 0; jo < 8; jo++) {
        const size_t col = hoff + jo * 8 + (lane & 3) * 2;
        uint32_t hp, lp;
        split2(O[jo][0] * il0, O[jo][1] * il0, hp, lp);
        *(uint32_t*)(Xh_ + r0 * DM + col) = hp;
        *(uint32_t*)(Xl_ + r0 * DM + col) = lp;
        split2(O[jo][2] * il1, O[jo][3] * il1, hp, lp);
        *(uint32_t*)(Xh_ + r1 * DM + col) = hp;
        *(uint32_t*)(Xl_ + r1 * DM + col) = lp;
    }
}

// ---------------------------------------------------------------------------
extern "C" void kernel_launch(void* const* d_in, const int* in_sizes, int n_in,
                              void* d_out, int out_size)
{
    const float* query = (const float*)d_in[0];
    const float* key   = (const float*)d_in[1];
    const float* value = (const float*)d_in[2];
    const float* Wq    = (const float*)d_in[3];
    const float* bq    = (const float*)d_in[4];
    const float* Wk    = (const float*)d_in[5];
    const float* bk    = (const float*)d_in[6];
    const float* Wv    = (const float*)d_in[7];
    const float* bv    = (const float*)d_in[8];
    const float* Wo    = (const float*)d_in[9];
    const float* bo    = (const float*)d_in[10];
    float* out = (float*)d_out;

    __nv_bfloat16 *qh, *ql, *kh, *kl, *vh, *vl, *xh, *xl;
    cudaGetSymbolAddress((void**)&qh, g_Qh);
    cudaGetSymbolAddress((void**)&ql, g_Ql);
    cudaGetSymbolAddress((void**)&kh, g_Kh);
    cudaGetSymbolAddress((void**)&kl, g_Kl);
    cudaGetSymbolAddress((void**)&vh, g_Vh);
    cudaGetSymbolAddress((void**)&vl, g_Vl);
    cudaGetSymbolAddress((void**)&xh, g_Xh);
    cudaGetSymbolAddress((void**)&xl, g_Xl);

    cudaFuncSetAttribute(qkv_gemm64,
                         cudaFuncAttributeMaxDynamicSharedMemorySize, GEMM_SMEM2);
    cudaFuncSetAttribute(out_gemm64,
                         cudaFuncAttributeMaxDynamicSharedMemorySize, GEMM_SMEM2);
    cudaFuncSetAttribute(attn_mma,
                         cudaFuncAttributeMaxDynamicSharedMemorySize, ATT_SMEM);

    // Fused splits
    split_inputs_kernel<<<dim3(2048, 1, 3), 256>>>(query, key, value);
    split_weights_kernel<<<dim3(512, 1, 4), 256>>>(Wq, Wk, Wv, Wo);

    // Fused QKV projections
    qkv_gemm64<<<dim3(DM / 128, MROWS / 128, 3), 256, GEMM_SMEM2>>>(bq, bk, bv);

    // Attention
    attn_mma<<<dim3(SS / 128, HH, BB), 256, ATT_SMEM>>>(qh, ql, kh, kl,
                                                        vh, vl, xh, xl);

    // Output projection
    out_gemm64<<<dim3(DM / 128, MROWS / 128), 256, GEMM_SMEM2>>>(bo, out);
}

// round 7
// speedup vs baseline: 3.3627x; 1.0005x over previous
#include <cuda_runtime.h>
#include <cuda_bf16.h>
#include <cstdint>

// Problem constants
#define BB 4
#define SS 2048
#define DM 1024
#define HH 16
#define HD 64
#define MROWS (BB * SS)   // 8192

// Q pre-scale: (1/sqrt(D)) * log2(e) folded into Q projection output.
#define QSCALE 0.04508422002778011f

// Scratch (allocation-free rule: __device__ globals)
__device__ __nv_bfloat16 g_Aqh[MROWS * DM], g_Aql[MROWS * DM];
__device__ __nv_bfloat16 g_Akh[MROWS * DM], g_Akl[MROWS * DM];
__device__ __nv_bfloat16 g_Avh[MROWS * DM], g_Avl[MROWS * DM];
__device__ __nv_bfloat16 g_Wqh[DM * DM], g_Wql[DM * DM];
__device__ __nv_bfloat16 g_Wkh[DM * DM], g_Wkl[DM * DM];
__device__ __nv_bfloat16 g_Wvh[DM * DM], g_Wvl[DM * DM];
__device__ __nv_bfloat16 g_Woh[DM * DM], g_Wol[DM * DM];
__device__ __nv_bfloat16 g_Qh[MROWS * DM], g_Ql[MROWS * DM];
__device__ __nv_bfloat16 g_Kh[MROWS * DM], g_Kl[MROWS * DM];
__device__ __nv_bfloat16 g_Vh[MROWS * DM], g_Vl[MROWS * DM];
__device__ __nv_bfloat16 g_Xh[MROWS * DM], g_Xl[MROWS * DM];

// ---------------------------------------------------------------------------
// Portable (sm_80+) tensor-core helpers
// ---------------------------------------------------------------------------
__device__ __forceinline__ uint32_t smem_to_u32(const void* p) {
    uint32_t a;
    asm("{ .reg .u64 t; cvta.to.shared.u64 t, %1; cvt.u32.u64 %0, t; }"
        : "=r"(a) : "l"(p));
    return a;
}

__device__ __forceinline__ void ldsm_x4(uint32_t& r0, uint32_t& r1,
                                        uint32_t& r2, uint32_t& r3,
                                        uint32_t addr) {
    asm volatile("ldmatrix.sync.aligned.m8n8.x4.shared.b16 {%0,%1,%2,%3}, [%4];"
                 : "=r"(r0), "=r"(r1), "=r"(r2), "=r"(r3) : "r"(addr));
}

__device__ __forceinline__ void ldsm_x4_t(uint32_t& r0, uint32_t& r1,
                                          uint32_t& r2, uint32_t& r3,
                                          uint32_t addr) {
    asm volatile("ldmatrix.sync.aligned.m8n8.x4.trans.shared.b16 {%0,%1,%2,%3}, [%4];"
                 : "=r"(r0), "=r"(r1), "=r"(r2), "=r"(r3) : "r"(addr));
}

__device__ __forceinline__ void mma_bf16(float* c, const uint32_t* a,
                                         uint32_t b0, uint32_t b1) {
    asm volatile(
        "mma.sync.aligned.m16n8k16.row.col.f32.bf16.bf16.f32 "
        "{%0,%1,%2,%3}, {%4,%5,%6,%7}, {%8,%9}, {%0,%1,%2,%3};"
        : "+f"(c[0]), "+f"(c[1]), "+f"(c[2]), "+f"(c[3])
        : "r"(a[0]), "r"(a[1]), "r"(a[2]), "r"(a[3]), "r"(b0), "r"(b1));
}

__device__ __forceinline__ float ex2(float x) {
    float y;
    asm("ex2.approx.ftz.f32 %0, %1;" : "=f"(y) : "f"(x));
    return y;
}

#define CP_ASYNC_16(smem_u32, gptr) \
    asm volatile("cp.async.cg.shared.global [%0], [%1], 16;" \
        :: "r"(smem_u32), "l"(gptr) : "memory")
#define CP_ASYNC_COMMIT() asm volatile("cp.async.commit_group;" ::: "memory")
#define CP_ASYNC_WAIT1() asm volatile("cp.async.wait_group 1;" ::: "memory")
#define CP_ASYNC_WAIT0() asm volatile("cp.async.wait_group 0;" ::: "memory")

// x = hi + lo (bf16 pair), packed two-at-a-time into bf16x2 registers
__device__ __forceinline__ void split2(float x, float y, uint32_t& hi, uint32_t& lo) {
    __nv_bfloat16 hx = __float2bfloat16_rn(x);
    __nv_bfloat16 hy = __float2bfloat16_rn(y);
    __nv_bfloat16 lx = __float2bfloat16_rn(x - __bfloat162float(hx));
    __nv_bfloat16 ly = __float2bfloat16_rn(y - __bfloat162float(hy));
    hi = ((uint32_t)__bfloat16_as_ushort(hy) << 16) | __bfloat16_as_ushort(hx);
    lo = ((uint32_t)__bfloat16_as_ushort(ly) << 16) | __bfloat16_as_ushort(lx);
}

__device__ __forceinline__ void split_body(const float* __restrict__ x,
                                           __nv_bfloat16* __restrict__ hi,
                                           __nv_bfloat16* __restrict__ lo, int n4)
{
    int i = blockIdx.x * blockDim.x + threadIdx.x;
    int stride = gridDim.x * blockDim.x;
    for (; i < n4; i += stride) {
        float4 v = ((const float4*)x)[i];
        uint32_t h0, l0, h1, l1;
        split2(v.x, v.y, h0, l0);
        split2(v.z, v.w, h1, l1);
        ((uint2*)hi)[i] = make_uint2(h0, h1);
        ((uint2*)lo)[i] = make_uint2(l0, l1);
    }
}

__global__ __launch_bounds__(256) void split_inputs_kernel(
    const float* __restrict__ q, const float* __restrict__ k,
    const float* __restrict__ v)
{
    const int n4 = MROWS * DM / 4;
    if (blockIdx.z == 0)      split_body(q, g_Aqh, g_Aql, n4);
    else if (blockIdx.z == 1) split_body(k, g_Akh, g_Akl, n4);
    else                      split_body(v, g_Avh, g_Avl, n4);
}

__global__ __launch_bounds__(256) void split_weights_kernel(
    const float* __restrict__ wq, const float* __restrict__ wk,
    const float* __restrict__ wv, const float* __restrict__ wo)
{
    const int n4 = DM * DM / 4;
    if (blockIdx.z == 0)      split_body(wq, g_Wqh, g_Wql, n4);
    else if (blockIdx.z == 1) split_body(wk, g_Wkh, g_Wkl, n4);
    else if (blockIdx.z == 2) split_body(wv, g_Wvh, g_Wvl, n4);
    else                      split_body(wo, g_Woh, g_Wol, n4);
}

// ---------------------------------------------------------------------------
// HMMA GEMM body (3-MMA bf16 split), BK=64, 3-stage cp.async pipeline.
// oscale: multiplies (acc + bias) before SPLIT_OUT write (Q pre-scaling).
// ---------------------------------------------------------------------------
#define SA2   72
#define TILE2 (128 * SA2 * 2)
#define STG2  (4 * TILE2)
#define GEMM_SMEM2 (3 * STG2)             // 221184 B
#define BKC2  64
#define NCH2  (DM / BKC2)                 // 16

template <bool SPLIT_OUT>
__device__ __forceinline__ void gemm64_body(
    const __nv_bfloat16* __restrict__ Ah, const __nv_bfloat16* __restrict__ Al,
    const __nv_bfloat16* __restrict__ Wh, const __nv_bfloat16* __restrict__ Wl,
    const float* __restrict__ bias, float oscale, float* __restrict__ C,
    __nv_bfloat16* __restrict__ Ch, __nv_bfloat16* __restrict__ Cl)
{
    extern __shared__ char smem[];
    const uint32_t sb = smem_to_u32(smem);
    const int tid  = threadIdx.x;
    const int wid  = tid >> 5;
    const int lane = tid & 31;
    const int bm = blockIdx.y * 128;
    const int bn = blockIdx.x * 128;
    const int wm = (wid >> 2) * 64;
    const int wn = (wid & 3) * 32;

    const int lrow  = tid >> 1;
    const int lcolb = (tid & 1) * 64;
    const char* gAh = (const char*)(Ah + (size_t)(bm + lrow) * DM) + lcolb;
    const char* gAl = (const char*)(Al + (size_t)(bm + lrow) * DM) + lcolb;
    const char* gBh = (const char*)(Wh + (size_t)(bn + lrow) * DM) + lcolb;
    const char* gBl = (const char*)(Wl + (size_t)(bn + lrow) * DM) + lcolb;
    const uint32_t so = (uint32_t)(lrow * SA2 * 2) + lcolb;

    auto load_chunk = [&](int c, int stg) {
        const uint32_t base = sb + stg * STG2;
        const int gb = c * (BKC2 * 2);
#pragma unroll
        for (int s = 0; s < 4; s++) {
            CP_ASYNC_16(base + 0 * TILE2 + so + s * 16, gAh + gb + s * 16);
            CP_ASYNC_16(base + 1 * TILE2 + so + s * 16, gAl + gb + s * 16);
            CP_ASYNC_16(base + 2 * TILE2 + so + s * 16, gBh + gb + s * 16);
            CP_ASYNC_16(base + 3 * TILE2 + so + s * 16, gBl + gb + s * 16);
        }
        CP_ASYNC_COMMIT();
    };

    const int grp = lane >> 3, rin = lane & 7;
    const int a_row = wm + (grp & 1) * 8 + rin;
    const int a_kof = (grp >> 1) * 8;
    const int b_row = wn + (grp >> 1) * 8 + rin;
    const int b_kof = (grp & 1) * 8;

    float acc[4][4][4];
#pragma unroll
    for (int i = 0; i < 4; i++)
#pragma unroll
        for (int j = 0; j < 4; j++)
#pragma unroll
            for (int r = 0; r < 4; r++) acc[i][j][r] = 0.0f;

    load_chunk(0, 0);
    load_chunk(1, 1);

    for (int c = 0; c < NCH2; c++) {
        if (c + 1 < NCH2) CP_ASYNC_WAIT1();
        else              CP_ASYNC_WAIT0();
        __syncthreads();
        if (c + 2 < NCH2) load_chunk(c + 2, (c + 2) % 3);

        const uint32_t base = sb + (c % 3) * STG2;
#pragma unroll
        for (int k0 = 0; k0 < BKC2; k0 += 16) {
            uint32_t ah[4][4], al[4][4], bh[4][2], bl[4][2];
#pragma unroll
            for (int i = 0; i < 4; i++) {
                uint32_t ad = base + 0 * TILE2 +
                    (uint32_t)((a_row + i * 16) * SA2 + k0 + a_kof) * 2;
                ldsm_x4(ah[i][0], ah[i][1], ah[i][2], ah[i][3], ad);
                ldsm_x4(al[i][0], al[i][1], al[i][2], al[i][3], ad + TILE2);
            }
#pragma unroll
            for (int jp = 0; jp < 2; jp++) {
                uint32_t bd = base + 2 * TILE2 +
                    (uint32_t)((b_row + jp * 16) * SA2 + k0 + b_kof) * 2;
                ldsm_x4(bh[jp * 2][0], bh[jp * 2][1],
                        bh[jp * 2 + 1][0], bh[jp * 2 + 1][1], bd);
                ldsm_x4(bl[jp * 2][0], bl[jp * 2][1],
                        bl[jp * 2 + 1][0], bl[jp * 2 + 1][1], bd + TILE2);
            }
#pragma unroll
            for (int i = 0; i < 4; i++)
#pragma unroll
                for (int j = 0; j < 4; j++) {
                    mma_bf16(acc[i][j], ah[i], bh[j][0], bh[j][1]);
                    mma_bf16(acc[i][j], ah[i], bl[j][0], bl[j][1]);
                    mma_bf16(acc[i][j], al[i], bh[j][0], bh[j][1]);
                }
        }
    }

    const int erow = bm + wm + (lane >> 2);
    const int ecol = bn + wn + (lane & 3) * 2;
#pragma unroll
    for (int i = 0; i < 4; i++) {
#pragma unroll
        for (int j = 0; j < 4; j++) {
            const int col = ecol + j * 8;
            const float b0 = bias[col], b1 = bias[col + 1];
            const size_t o0 = (size_t)(erow + i * 16) * DM + col;
            const size_t o1 = (size_t)(erow + i * 16 + 8) * DM + col;
            if (SPLIT_OUT) {
                uint32_t hv, lv;
                split2((acc[i][j][0] + b0) * oscale,
                       (acc[i][j][1] + b1) * oscale, hv, lv);
                *(uint32_t*)(Ch + o0) = hv;
                *(uint32_t*)(Cl + o0) = lv;
                split2((acc[i][j][2] + b0) * oscale,
                       (acc[i][j][3] + b1) * oscale, hv, lv);
                *(uint32_t*)(Ch + o1) = hv;
                *(uint32_t*)(Cl + o1) = lv;
            } else {
                *(float2*)(C + o0) =
                    make_float2(acc[i][j][0] + b0, acc[i][j][1] + b1);
                *(float2*)(C + o1) =
                    make_float2(acc[i][j][2] + b0, acc[i][j][3] + b1);
            }
        }
    }
}

__global__ __launch_bounds__(256, 1) void qkv_gemm64(
    const float* __restrict__ bq, const float* __restrict__ bk,
    const float* __restrict__ bv)
{
    if (blockIdx.z == 0)
        gemm64_body<true>(g_Aqh, g_Aql, g_Wqh, g_Wql, bq, QSCALE,
                          nullptr, g_Qh, g_Ql);
    else if (blockIdx.z == 1)
        gemm64_body<true>(g_Akh, g_Akl, g_Wkh, g_Wkl, bk, 1.0f,
                          nullptr, g_Kh, g_Kl);
    else
        gemm64_body<true>(g_Avh, g_Avl, g_Wvh, g_Wvl, bv, 1.0f,
                          nullptr, g_Vh, g_Vl);
}

__global__ __launch_bounds__(256, 1) void out_gemm64(
    const float* __restrict__ bo, float* __restrict__ out)
{
    gemm64_body<false>(g_Xh, g_Xl, g_Woh, g_Wol, bo, 1.0f,
                       out, nullptr, nullptr);
}

// ---------------------------------------------------------------------------
// HMMA flash attention. Q pre-scaled by (1/32)*log2e -> softmax in exp2 domain.
// Q fragments hoisted to registers before the kt loop.
// ---------------------------------------------------------------------------
#define ASA 72
#define ATILE (128 * ASA * 2)
#define A_QH 0
#define A_QL ATILE
#define A_ST0 (2 * ATILE)
#define A_STAGE (4 * ATILE)
#define ATT_SMEM (2 * ATILE + 2 * A_STAGE)   // 184320 B
#define NKT (SS / 128)

__global__ __launch_bounds__(256, 1) void attn_mma(
    const __nv_bfloat16* __restrict__ Qh_, const __nv_bfloat16* __restrict__ Ql_,
    const __nv_bfloat16* __restrict__ Kh_, const __nv_bfloat16* __restrict__ Kl_,
    const __nv_bfloat16* __restrict__ Vh_, const __nv_bfloat16* __restrict__ Vl_,
    __nv_bfloat16* __restrict__ Xh_, __nv_bfloat16* __restrict__ Xl_)
{
    extern __shared__ char smem[];
    const uint32_t sb = smem_to_u32(smem);
    const int tid  = threadIdx.x;
    const int wid  = tid >> 5;
    const int lane = tid & 31;
    const int qm   = wid * 16;
    const int qb = blockIdx.x, h = blockIdx.y, b = blockIdx.z;
    const size_t qrow0 = (size_t)(b * SS + qb * 128);
    const size_t hoff  = (size_t)h * HD;

    // Q tile (hi+lo) via cp.async (group 0)
#pragma unroll
    for (int i = 0; i < 4; i++) {
        int ci = tid + i * 256;
        int r = ci >> 3, cof = (ci & 7) * 16;
        uint32_t so = (uint32_t)(r * ASA * 2) + cof;
        CP_ASYNC_16(sb + A_QH + so,
                    (const char*)(Qh_ + (qrow0 + r) * DM + hoff) + cof);
        CP_ASYNC_16(sb + A_QL + so,
                    (const char*)(Ql_ + (qrow0 + r) * DM + hoff) + cof);
    }
    CP_ASYNC_COMMIT();

    auto load_kv = [&](int kt, int stg) {
        const size_t k0 = (size_t)(b * SS + kt * 128);
        const uint32_t base = sb + A_ST0 + stg * A_STAGE;
#pragma unroll
        for (int i = 0; i < 4; i++) {
            int ci = tid + i * 256;
            int r = ci >> 3, cof = (ci & 7) * 16;
            uint32_t so = (uint32_t)(r * ASA * 2) + cof;
            const size_t g = (k0 + r) * DM + hoff;
            CP_ASYNC_16(base + 0 * ATILE + so, (const char*)(Kh_ + g) + cof);
            CP_ASYNC_16(base + 1 * ATILE + so, (const char*)(Kl_ + g) + cof);
            CP_ASYNC_16(base + 2 * ATILE + so, (const char*)(Vh_ + g) + cof);
            CP_ASYNC_16(base + 3 * ATILE + so, (const char*)(Vl_ + g) + cof);
        }
        CP_ASYNC_COMMIT();
    };

    load_kv(0, 0);    // group 1

    // ldmatrix lane address components
    const int qrow_f = qm + (lane & 7) + ((lane >> 3) & 1) * 8;
    const int qkof_f = ((lane >> 4) & 1) * 8;
    const int krow_f = (lane & 7) + ((lane >> 4) & 1) * 8;
    const int kkof_f = ((lane >> 3) & 1) * 8;
    const int vrow_f = lane & 15;
    const int vcol_f = (lane >> 4) * 8;

    // Hoist Q fragments to registers (Q group done after WAIT1)
    CP_ASYNC_WAIT1();
    __syncthreads();
    uint32_t qfh[4][4], qfl[4][4];
#pragma unroll
    for (int ks = 0; ks < 4; ks++) {
        uint32_t qa = sb + A_QH + (uint32_t)(qrow_f * ASA + qkof_f + ks * 16) * 2;
        ldsm_x4(qfh[ks][0], qfh[ks][1], qfh[ks][2], qfh[ks][3], qa);
        ldsm_x4(qfl[ks][0], qfl[ks][1], qfl[ks][2], qfl[ks][3], qa + ATILE);
    }

    float O[8][4];
#pragma unroll
    for (int jo = 0; jo < 8; jo++)
#pragma unroll
        for (int r = 0; r < 4; r++) O[jo][r] = 0.0f;
    float M0 = -3.0e38f, M1 = -3.0e38f, L0 = 0.0f, L1 = 0.0f;

    for (int kt = 0; kt < NKT; kt++) {
        if (kt + 1 < NKT) {
            load_kv(kt + 1, (kt + 1) & 1);
            CP_ASYNC_WAIT1();
        } else {
            CP_ASYNC_WAIT0();
        }
        __syncthreads();
        const uint32_t stage = sb + A_ST0 + (kt & 1) * A_STAGE;

        // ---- S = Q @ K^T (3-MMA split); scores already in exp2 domain ----
        float s[16][4];
#pragma unroll
        for (int j = 0; j < 16; j++)
#pragma unroll
            for (int r = 0; r < 4; r++) s[j][r] = 0.0f;

#pragma unroll
        for (int ks = 0; ks < 4; ks++) {
#pragma unroll
            for (int jp = 0; jp < 8; jp++) {
                uint32_t kh[4], kl[4];
                uint32_t ka = stage + 0 * ATILE +
                    (uint32_t)((krow_f + jp * 16) * ASA + kkof_f + ks * 16) * 2;
                ldsm_x4(kh[0], kh[1], kh[2], kh[3], ka);
                ldsm_x4(kl[0], kl[1], kl[2], kl[3], ka + ATILE);
                mma_bf16(s[jp * 2],     qfh[ks], kh[0], kh[1]);
                mma_bf16(s[jp * 2],     qfh[ks], kl[0], kl[1]);
                mma_bf16(s[jp * 2],     qfl[ks], kh[0], kh[1]);
                mma_bf16(s[jp * 2 + 1], qfh[ks], kh[2], kh[3]);
                mma_bf16(s[jp * 2 + 1], qfh[ks], kl[2], kl[3]);
                mma_bf16(s[jp * 2 + 1], qfl[ks], kh[2], kh[3]);
            }
        }

        // ---- online softmax (exp2 domain) ----
        float mx0 = -3.0e38f, mx1 = -3.0e38f;
#pragma unroll
        for (int j = 0; j < 16; j++) {
            mx0 = fmaxf(mx0, fmaxf(s[j][0], s[j][1]));
            mx1 = fmaxf(mx1, fmaxf(s[j][2], s[j][3]));
        }
        mx0 = fmaxf(mx0, __shfl_xor_sync(0xffffffffu, mx0, 1));
        mx0 = fmaxf(mx0, __shfl_xor_sync(0xffffffffu, mx0, 2));
        mx1 = fmaxf(mx1, __shfl_xor_sync(0xffffffffu, mx1, 1));
        mx1 = fmaxf(mx1, __shfl_xor_sync(0xffffffffu, mx1, 2));

        const float Mn0 = fmaxf(M0, mx0), Mn1 = fmaxf(M1, mx1);
        const float f0 = ex2(M0 - Mn0), f1 = ex2(M1 - Mn1);
        M0 = Mn0; M1 = Mn1;

        float sum0 = 0.0f, sum1 = 0.0f;
#pragma unroll
        for (int j = 0; j < 16; j++) {
            s[j][0] = ex2(s[j][0] - M0);
            s[j][1] = ex2(s[j][1] - M0);
            s[j][2] = ex2(s[j][2] - M1);
            s[j][3] = ex2(s[j][3] - M1);
            sum0 += s[j][0] + s[j][1];
            sum1 += s[j][2] + s[j][3];
        }
        sum0 += __shfl_xor_sync(0xffffffffu, sum0, 1);
        sum0 += __shfl_xor_sync(0xffffffffu, sum0, 2);
        sum1 += __shfl_xor_sync(0xffffffffu, sum1, 1);
        sum1 += __shfl_xor_sync(0xffffffffu, sum1, 2);
        L0 = L0 * f0 + sum0;
        L1 = L1 * f1 + sum1;

#pragma unroll
        for (int jo = 0; jo < 8; jo++) {
            O[jo][0] *= f0; O[jo][1] *= f0;
            O[jo][2] *= f1; O[jo][3] *= f1;
        }

        // ---- O += P @ V (3-MMA split) ----
#pragma unroll
        for (int ks2 = 0; ks2 < 8; ks2++) {
            uint32_t ah[4], al[4];
            split2(s[2 * ks2][0],     s[2 * ks2][1],     ah[0], al[0]);
            split2(s[2 * ks2][2],     s[2 * ks2][3],     ah[1], al[1]);
            split2(s[2 * ks2 + 1][0], s[2 * ks2 + 1][1], ah[2], al[2]);
            split2(s[2 * ks2 + 1][2], s[2 * ks2 + 1][3], ah[3], al[3]);
#pragma unroll
            for (int nn = 0; nn < 4; nn++) {
                uint32_t vh[4], vl[4];
                uint32_t va = stage + 2 * ATILE +
                    (uint32_t)((ks2 * 16 + vrow_f) * ASA + nn * 16 + vcol_f) * 2;
                ldsm_x4_t(vh[0], vh[1], vh[2], vh[3], va);
                ldsm_x4_t(vl[0], vl[1], vl[2], vl[3], va + ATILE);
                mma_bf16(O[nn * 2],     ah, vh[0], vh[1]);
                mma_bf16(O[nn * 2],     ah, vl[0], vl[1]);
                mma_bf16(O[nn * 2],     al, vh[0], vh[1]);
                mma_bf16(O[nn * 2 + 1], ah, vh[2], vh[3]);
                mma_bf16(O[nn * 2 + 1], ah, vl[2], vl[3]);
                mma_bf16(O[nn * 2 + 1], al, vh[2], vh[3]);
            }
        }
        __syncthreads();
    }

    const float il0 = 1.0f / L0, il1 = 1.0f / L1;
    const size_t r0 = qrow0 + qm + (lane >> 2);
    const size_t r1 = r0 + 8;
#pragma unroll
    for (int jo = 0; jo < 8; jo++) {
        const size_t col = hoff + jo * 8 + (lane & 3) * 2;
        uint32_t hp, lp;
        split2(O[jo][0] * il0, O[jo][1] * il0, hp, lp);
        *(uint32_t*)(Xh_ + r0 * DM + col) = hp;
        *(uint32_t*)(Xl_ + r0 * DM + col) = lp;
        split2(O[jo][2] * il1, O[jo][3] * il1, hp, lp);
        *(uint32_t*)(Xh_ + r1 * DM + col) = hp;
        *(uint32_t*)(Xl_ + r1 * DM + col) = lp;
    }
}

// ---------------------------------------------------------------------------
extern "C" void kernel_launch(void* const* d_in, const int* in_sizes, int n_in,
                              void* d_out, int out_size)
{
    const float* query = (const float*)d_in[0];
    const float* key   = (const float*)d_in[1];
    const float* value = (const float*)d_in[2];
    const float* Wq    = (const float*)d_in[3];
    const float* bq    = (const float*)d_in[4];
    const float* Wk    = (const float*)d_in[5];
    const float* bk    = (const float*)d_in[6];
    const float* Wv    = (const float*)d_in[7];
    const float* bv    = (const float*)d_in[8];
    const float* Wo    = (const float*)d_in[9];
    const float* bo    = (const float*)d_in[10];
    float* out = (float*)d_out;

    __nv_bfloat16 *qh, *ql, *kh, *kl, *vh, *vl, *xh, *xl;
    cudaGetSymbolAddress((void**)&qh, g_Qh);
    cudaGetSymbolAddress((void**)&ql, g_Ql);
    cudaGetSymbolAddress((void**)&kh, g_Kh);
    cudaGetSymbolAddress((void**)&kl, g_Kl);
    cudaGetSymbolAddress((void**)&vh, g_Vh);
    cudaGetSymbolAddress((void**)&vl, g_Vl);
    cudaGetSymbolAddress((void**)&xh, g_Xh);
    cudaGetSymbolAddress((void**)&xl, g_Xl);

    cudaFuncSetAttribute(qkv_gemm64,
                         cudaFuncAttributeMaxDynamicSharedMemorySize, GEMM_SMEM2);
    cudaFuncSetAttribute(out_gemm64,
                         cudaFuncAttributeMaxDynamicSharedMemorySize, GEMM_SMEM2);
    cudaFuncSetAttribute(attn_mma,
                         cudaFuncAttributeMaxDynamicSharedMemorySize, ATT_SMEM);

    split_inputs_kernel<<<dim3(2048, 1, 3), 256>>>(query, key, value);
    split_weights_kernel<<<dim3(512, 1, 4), 256>>>(Wq, Wk, Wv, Wo);

    qkv_gemm64<<<dim3(DM / 128, MROWS / 128, 3), 256, GEMM_SMEM2>>>(bq, bk, bv);

    attn_mma<<<dim3(SS / 128, HH, BB), 256, ATT_SMEM>>>(qh, ql, kh, kl,
                                                        vh, vl, xh, xl);

    out_gemm64<<<dim3(DM / 128, MROWS / 128), 256, GEMM_SMEM2>>>(bo, out);
}